// round 10
// baseline (speedup 1.0000x reference)
#include <cuda_runtime.h>
#include <math.h>
#include <stdint.h>

#define BB 4
#define TT 4096
#define DD 1024
#define NO 256      // 2*dv
#define NROW (BB*TT)
#define LN_EPS_F 1e-5f
#define LAMBDA_INIT 0.3555090675909693f
#define ATT_SCALE 0.0883883476483184405f   // 1/sqrt(128)

typedef unsigned long long u64;

// packed f32x2 helpers (sm_100+ PTX; SASS FFMA2/FADD2)
#define FFMA2(d, a, b) asm("fma.rn.f32x2 %0, %1, %2, %0;" : "+l"(d) : "l"(a), "l"(b))
#define FADD2(d, a)    asm("add.rn.f32x2 %0, %0, %1;"     : "+l"(d) : "l"(a))
#define PACK2(d, x)    asm("mov.b64 %0, {%1, %1};" : "=l"(d) : "r"(__float_as_uint(x)))
#define PACKAB(d, x, y) asm("mov.b64 %0, {%1, %2};" : "=l"(d) : "r"(__float_as_uint(x)), "r"(__float_as_uint(y)))
#define UNPACK2(lo, hi, v) do { unsigned _ul, _uh; \
    asm("mov.b64 {%0, %1}, %2;" : "=r"(_ul), "=r"(_uh) : "l"(v)); \
    (lo) = __uint_as_float(_ul); (hi) = __uint_as_float(_uh); } while (0)

#define CPASYNC16(dst, src) \
    asm volatile("cp.async.cg.shared.global [%0], [%1], 16;" :: "r"(dst), "l"(src) : "memory")
#define CPCOMMIT() asm volatile("cp.async.commit_group;" ::: "memory")
#define CPWAIT0()  asm volatile("cp.async.wait_group 0;" ::: "memory")

__device__ __forceinline__ uint32_t smem_u32(const void* p) {
    uint32_t a;
    asm("{ .reg .u64 t; cvta.to.shared.u64 t, %1; cvt.u32.u64 %0, t; }" : "=r"(a) : "l"(p));
    return a;
}

// scratch (device globals: allocation-free rule)
__device__ float g_Q[NROW * NO];
__device__ float g_K[NROW * NO];
__device__ float g_V[NROW * NO];
__device__ float g_lambda;

// ---------------------------------------------------------------------------
// Kernel 1: uniform QKV GEMM (proven round-7 version, unchanged).
// ---------------------------------------------------------------------------
__global__ __launch_bounds__(256) void qkv_gemm(
    const float* __restrict__ x,
    const float* __restrict__ Wq,
    const float* __restrict__ Wk,
    const float* __restrict__ Wv)
{
    __shared__ float Xs[16][132];
    __shared__ float Ws[16][128];

    const int nt  = blockIdx.x;
    const int mt  = blockIdx.y;
    const int mat = nt >> 1;
    const int n0  = (nt & 1) * 128;
    const float* W = (mat == 0) ? Wq : ((mat == 1) ? Wk : Wv);
    float* Out     = (mat == 0) ? g_Q : ((mat == 1) ? g_K : g_V);

    const int m0  = mt * 128;
    const int tid = threadIdx.x;
    const int tx  = tid & 15;
    const int ty  = tid >> 4;

    const int xrow = tid >> 2;
    const int xkc  = tid & 3;
    const int wkr  = tid >> 5;
    const int wnc  = tid & 31;

    const float* xp0 = x + (size_t)(m0 + xrow) * DD + xkc * 4;
    const float* xp1 = x + (size_t)(m0 + xrow + 64) * DD + xkc * 4;
    const float* wp0 = W + (size_t)wkr * NO + n0 + wnc * 4;
    const float* wp1 = W + (size_t)(wkr + 8) * NO + n0 + wnc * 4;

    u64 c[4][8];
#pragma unroll
    for (int i = 0; i < 4; i++)
#pragma unroll
        for (int j = 0; j < 8; j++) c[i][j] = 0ull;

    float4 xr0 = *(const float4*)xp0;
    float4 xr1 = *(const float4*)xp1;
    float4 wr0 = *(const float4*)wp0;
    float4 wr1 = *(const float4*)wp1;

    for (int k0 = 0; k0 < DD; k0 += 16) {
        Xs[xkc * 4 + 0][xrow]      = xr0.x;
        Xs[xkc * 4 + 1][xrow]      = xr0.y;
        Xs[xkc * 4 + 2][xrow]      = xr0.z;
        Xs[xkc * 4 + 3][xrow]      = xr0.w;
        Xs[xkc * 4 + 0][xrow + 64] = xr1.x;
        Xs[xkc * 4 + 1][xrow + 64] = xr1.y;
        Xs[xkc * 4 + 2][xrow + 64] = xr1.z;
        Xs[xkc * 4 + 3][xrow + 64] = xr1.w;
        *(float4*)(&Ws[wkr][wnc * 4])     = wr0;
        *(float4*)(&Ws[wkr + 8][wnc * 4]) = wr1;
        __syncthreads();

        if (k0 + 16 < DD) {
            xr0 = *(const float4*)(xp0 + k0 + 16);
            xr1 = *(const float4*)(xp1 + k0 + 16);
            wr0 = *(const float4*)(wp0 + (size_t)(k0 + 16) * NO);
            wr1 = *(const float4*)(wp1 + (size_t)(k0 + 16) * NO);
        }

#pragma unroll
        for (int kk = 0; kk < 16; kk++) {
            ulonglong2 A0 = *(const ulonglong2*)(&Xs[kk][ty * 4]);
            ulonglong2 A1 = *(const ulonglong2*)(&Xs[kk][64 + ty * 4]);
            float4 b0 = *(const float4*)(&Ws[kk][tx * 4]);
            float4 b1 = *(const float4*)(&Ws[kk][64 + tx * 4]);
            u64 B[8];
            PACK2(B[0], b0.x); PACK2(B[1], b0.y); PACK2(B[2], b0.z); PACK2(B[3], b0.w);
            PACK2(B[4], b1.x); PACK2(B[5], b1.y); PACK2(B[6], b1.z); PACK2(B[7], b1.w);
#pragma unroll
            for (int j = 0; j < 8; j++) {
                FFMA2(c[0][j], A0.x, B[j]);
                FFMA2(c[1][j], A0.y, B[j]);
                FFMA2(c[2][j], A1.x, B[j]);
                FFMA2(c[3][j], A1.y, B[j]);
            }
        }
        __syncthreads();
    }

#pragma unroll
    for (int rp = 0; rp < 4; rp++) {
        const int r = (rp < 2) ? (ty * 4 + rp * 2) : (64 + ty * 4 + (rp - 2) * 2);
        float lo[8], hi[8];
#pragma unroll
        for (int j = 0; j < 8; j++) UNPACK2(lo[j], hi[j], c[rp][j]);
        float* o0 = Out + (size_t)(m0 + r) * NO + n0;
        float* o1 = o0 + NO;
        *(float4*)(o0 + tx * 4)      = make_float4(lo[0], lo[1], lo[2], lo[3]);
        *(float4*)(o0 + 64 + tx * 4) = make_float4(lo[4], lo[5], lo[6], lo[7]);
        *(float4*)(o1 + tx * 4)      = make_float4(hi[0], hi[1], hi[2], hi[3]);
        *(float4*)(o1 + 64 + tx * 4) = make_float4(hi[4], hi[5], hi[6], hi[7]);
    }
}

// ---------------------------------------------------------------------------
// Kernel 2: recompute the 64 state rows with the *_state weights.
// ---------------------------------------------------------------------------
__global__ __launch_bounds__(256) void state_fixup(
    const float* __restrict__ x,
    const float* __restrict__ Wqs,
    const float* __restrict__ Wks,
    const float* __restrict__ Wvs)
{
    __shared__ float xs[DD];
    const int id = blockIdx.x;
    const int b  = id >> 4;
    const int i  = id & 15;
    const int t  = (i < 8) ? i : (TT - 16 + i);
    const size_t row = (size_t)b * TT + t;
    const int tid = threadIdx.x;

    for (int d = tid; d < DD; d += 256) xs[d] = x[row * DD + d];
    __syncthreads();

    float aq = 0.f, ak = 0.f, av = 0.f;
    const int n = tid;
#pragma unroll 4
    for (int d = 0; d < DD; d++) {
        float xv = xs[d];
        aq += xv * Wqs[(size_t)d * NO + n];
        ak += xv * Wks[(size_t)d * NO + n];
        av += xv * Wvs[(size_t)d * NO + n];
    }
    g_Q[row * NO + n] = aq;
    g_K[row * NO + n] = ak;
    g_V[row * NO + n] = av;
}

// ---------------------------------------------------------------------------
// Kernel 3: lambda scalar
// ---------------------------------------------------------------------------
__global__ void lambda_kernel(const float* __restrict__ lq1,
                              const float* __restrict__ lq2,
                              const float* __restrict__ lk1,
                              const float* __restrict__ lk2)
{
    int lane = threadIdx.x;
    float s1 = 0.f, s2 = 0.f;
    for (int i = lane; i < 128; i += 32) {
        s1 += lq1[i] * lk1[i];
        s2 += lq2[i] * lk2[i];
    }
#pragma unroll
    for (int o = 16; o > 0; o >>= 1) {
        s1 += __shfl_xor_sync(0xffffffffu, s1, o);
        s2 += __shfl_xor_sync(0xffffffffu, s2, o);
    }
    if (lane == 0) g_lambda = expf(s1) - expf(s2) + LAMBDA_INIT;
}

// ---------------------------------------------------------------------------
// Kernel 4: fused differential causal attention + combine + LayerNorm.
// 64-row tiles, 256 threads, head-split (warps 0-3 head1 / 4-7 head2,
// 16 rows each), cp.async DOUBLE-BUFFERED K/V pipeline, 1 CTA/SM.
// Pair-balanced tiles (x, 63-x): 130 chunks per CTA, grid 128 = one wave.
// smem (float4 units):
//   qp   [0     .. 4096)  packed Q row-pairs (32 pairs x 256 u64)
//   ks0  [4096  .. 6176)  K chunk buf0 (32 x 65)
//   ks1  [6176  .. 8256)  K chunk buf1
//   vs0  [8256  .. 10304) V chunk buf0 (32 x 64)
//   vs1  [10304 .. 12352) V chunk buf1
//   ps   [12352 .. 13632) P stash (8 warps x 32 keys x 20 floats)
//   ex aliases ks0/ks1 (64 rows x 256 floats) for the head combine.
// ---------------------------------------------------------------------------
#define SM_KS0 4096
#define SM_KS1 6176
#define SM_VS0 8256
#define SM_VS1 10304
#define SM_PS  12352
#define SM_TOTAL_F4 13632          // * 16B = 218112 bytes

__device__ __forceinline__ void stage_chunk(
    uint32_t ksb, uint32_t vsb, size_t rowbase, int tid)
{
#pragma unroll
    for (int i = 0; i < 8; i++) {
        int idx = tid + (i << 8);
        int key = idx >> 6;
        int d4  = idx & 63;
        const float* ksrc = g_K + (rowbase + key) * NO + d4 * 4;
        const float* vsrc = g_V + (rowbase + key) * NO + d4 * 4;
        uint32_t kdst = ksb + (uint32_t)(key * 65 + d4) * 16;
        uint32_t vdst = vsb + (uint32_t)(key * 64 + d4) * 16;
        CPASYNC16(kdst, ksrc);
        CPASYNC16(vdst, vsrc);
    }
    CPCOMMIT();
}

__global__ __launch_bounds__(256, 1) void attn_kernel(
    float* __restrict__ out,
    const float* __restrict__ ln_gamma,
    const float* __restrict__ ln_beta)
{
    extern __shared__ float4 sm[];
    u64*   qp = (u64*)sm;
    float* ps = (float*)(sm + SM_PS);
    float* ex = (float*)(sm + SM_KS0);
    const uint32_t smem_base = smem_u32(sm);
    const uint32_t ksb0 = smem_base + SM_KS0 * 16;
    const uint32_t ksb1 = smem_base + SM_KS1 * 16;
    const uint32_t vsb0 = smem_base + SM_VS0 * 16;
    const uint32_t vsb1 = smem_base + SM_VS1 * 16;

    const int b    = blockIdx.y;
    const int tid  = threadIdx.x;
    const int warp = tid >> 5;
    const int lane = tid & 31;
    const int h    = warp >> 2;          // 0 = head1, 1 = head2
    const int hw   = warp & 3;
    const size_t base = (size_t)b * TT;
    const float lamv = g_lambda;

    float g[8], bt[8];
#pragma unroll
    for (int k = 0; k < 4; k++) {
        g[k]      = ln_gamma[lane * 4 + k];
        g[4 + k]  = ln_gamma[128 + lane * 4 + k];
        bt[k]     = ln_beta[lane * 4 + k];
        bt[4 + k] = ln_beta[128 + lane * 4 + k];
    }

    const int r0 = hw * 16;              // first of 16 rows for this warp
    float* psw = ps + warp * 640;
    const u64* qb = qp + (hw * 8) * 256 + h * 128;   // this warp's 8 pairs

#pragma unroll 1
    for (int pass = 0; pass < 2; pass++) {
        const int tile = pass ? (63 - blockIdx.x) : blockIdx.x;
        const int t0   = tile * 64;
        const int nch  = 2 * tile + 2;

        __syncthreads();   // previous pass fully done with smem (incl. ex reads)

        // prefetch chunk 0 into buffer 0 (overlaps Q packing below)
        stage_chunk(ksb0, vsb0, base, tid);

        // stage Q tile (64 rows) as packed row-pairs, pre-scaled by 1/sqrt(dk)
        for (int idx = tid; idx < 32 * 64; idx += 256) {
            int p  = idx >> 6;
            int dg = idx & 63;
            const float* r0p = g_Q + (base + t0 + 2 * p) * NO + dg * 4;
            float4 a = *(const float4*)r0p;
            float4 c = *(const float4*)(r0p + NO);
            u64 w0, w1, w2, w3;
            PACKAB(w0, a.x * ATT_SCALE, c.x * ATT_SCALE);
            PACKAB(w1, a.y * ATT_SCALE, c.y * ATT_SCALE);
            PACKAB(w2, a.z * ATT_SCALE, c.z * ATT_SCALE);
            PACKAB(w3, a.w * ATT_SCALE, c.w * ATT_SCALE);
            u64* dst = qp + p * 256 + dg * 4;
            dst[0] = w0; dst[1] = w1; dst[2] = w2; dst[3] = w3;
        }

        float l[16];
        u64 acc[16][4];
#pragma unroll
        for (int r = 0; r < 16; r++) {
            l[r] = 0.f;
            acc[r][0] = 0ull; acc[r][1] = 0ull;
            acc[r][2] = 0ull; acc[r][3] = 0ull;
        }

        for (int c = 0; c < nch; c++) {
            const int kb = c << 5;
            CPWAIT0();
            __syncthreads();
            if (c + 1 < nch)
                stage_chunk((c & 1) ? ksb0 : ksb1, (c & 1) ? vsb0 : vsb1,
                            base + ((size_t)(c + 1) << 5), tid);

            const float4* ks = sm + ((c & 1) ? SM_KS1 : SM_KS0);
            const float4* vs = sm + ((c & 1) ? SM_VS1 : SM_VS0);

            if (kb <= t0 + r0 + 15) {
                // scores: 8 row-pairs, this warp's head half of K
                u64 se[8], so[8];
#pragma unroll
                for (int pp = 0; pp < 8; pp++) { se[pp] = 0ull; so[pp] = 0ull; }
                const float4* kp = ks + lane * 65 + h * 32;
#pragma unroll 4
                for (int gg = 0; gg < 32; gg++) {
                    float4 kf = kp[gg];
                    u64 k0, k1, k2, k3;
                    PACK2(k0, kf.x); PACK2(k1, kf.y);
                    PACK2(k2, kf.z); PACK2(k3, kf.w);
#pragma unroll
                    for (int pp = 0; pp < 8; pp++) {
                        const u64* qq = qb + pp * 256 + gg * 4;
                        ulonglong2 a0 = *(const ulonglong2*)qq;
                        ulonglong2 a1 = *(const ulonglong2*)(qq + 2);
                        FFMA2(se[pp], k0, a0.x); FFMA2(so[pp], k1, a0.y);
                        FFMA2(se[pp], k2, a1.x); FFMA2(so[pp], k3, a1.y);
                    }
                }
                float sc[16];
#pragma unroll
                for (int pp = 0; pp < 8; pp++) {
                    FADD2(se[pp], so[pp]);
                    UNPACK2(sc[2 * pp], sc[2 * pp + 1], se[pp]);
                }

                // p = exp(score), causal-masked; lane-local denominators
                const int key = kb + lane;
                float pw[16];
#pragma unroll
                for (int ri = 0; ri < 16; ri++) {
                    const int tg = t0 + r0 + ri;
                    float p = (key <= tg) ? __expf(sc[ri]) : 0.f;
                    l[ri] += p;
                    pw[ri] = p;
                }
                float* pl = psw + lane * 20;
                *(float4*)(pl)      = make_float4(pw[0],  pw[1],  pw[2],  pw[3]);
                *(float4*)(pl + 4)  = make_float4(pw[4],  pw[5],  pw[6],  pw[7]);
                *(float4*)(pl + 8)  = make_float4(pw[8],  pw[9],  pw[10], pw[11]);
                *(float4*)(pl + 12) = make_float4(pw[12], pw[13], pw[14], pw[15]);
                __syncwarp();

                // P @ V: 16 rows share each V read
#pragma unroll 2
                for (int j = 0; j < 32; j++) {
                    ulonglong2 v0 = *(const ulonglong2*)(vs + j * 64 + lane);
                    ulonglong2 v1 = *(const ulonglong2*)(vs + j * 64 + 32 + lane);
                    const float* pj = psw + j * 20;
                    float4 pa = *(const float4*)(pj);
                    float4 pb = *(const float4*)(pj + 4);
                    float4 pc = *(const float4*)(pj + 8);
                    float4 pd = *(const float4*)(pj + 12);
                    u64 w;
                    PACK2(w, pa.x);
                    FFMA2(acc[0][0], w, v0.x); FFMA2(acc[0][1], w, v0.y);
                    FFMA2(acc[0][2], w, v1.x); FFMA2(acc[0][3], w, v1.y);
                    PACK2(w, pa.y);
                    FFMA2(acc[1][0], w, v0.x); FFMA2(acc[1][1], w, v0.y);
                    FFMA2(acc[1][2], w, v1.x); FFMA2(acc[1][3], w, v1.y);
                    PACK2(w, pa.z);
                    FFMA2(acc[2][0], w, v0.x); FFMA2(acc[2][1], w, v0.y);
                    FFMA2(acc[2][2], w, v1.x); FFMA2(acc[2][3], w, v1.y);
                    PACK2(w, pa.w);
                    FFMA2(acc[3][0], w, v0.x); FFMA2(acc[3][1], w, v0.y);
                    FFMA2(acc[3][2], w, v1.x); FFMA2(acc[3][3], w, v1.y);
                    PACK2(w, pb.x);
                    FFMA2(acc[4][0], w, v0.x); FFMA2(acc[4][1], w, v0.y);
                    FFMA2(acc[4][2], w, v1.x); FFMA2(acc[4][3], w, v1.y);
                    PACK2(w, pb.y);
                    FFMA2(acc[5][0], w, v0.x); FFMA2(acc[5][1], w, v0.y);
                    FFMA2(acc[5][2], w, v1.x); FFMA2(acc[5][3], w, v1.y);
                    PACK2(w, pb.z);
                    FFMA2(acc[6][0], w, v0.x); FFMA2(acc[6][1], w, v0.y);
                    FFMA2(acc[6][2], w, v1.x); FFMA2(acc[6][3], w, v1.y);
                    PACK2(w, pb.w);
                    FFMA2(acc[7][0], w, v0.x); FFMA2(acc[7][1], w, v0.y);
                    FFMA2(acc[7][2], w, v1.x); FFMA2(acc[7][3], w, v1.y);
                    PACK2(w, pc.x);
                    FFMA2(acc[8][0], w, v0.x); FFMA2(acc[8][1], w, v0.y);
                    FFMA2(acc[8][2], w, v1.x); FFMA2(acc[8][3], w, v1.y);
                    PACK2(w, pc.y);
                    FFMA2(acc[9][0], w, v0.x); FFMA2(acc[9][1], w, v0.y);
                    FFMA2(acc[9][2], w, v1.x); FFMA2(acc[9][3], w, v1.y);
                    PACK2(w, pc.z);
                    FFMA2(acc[10][0], w, v0.x); FFMA2(acc[10][1], w, v0.y);
                    FFMA2(acc[10][2], w, v1.x); FFMA2(acc[10][3], w, v1.y);
                    PACK2(w, pc.w);
                    FFMA2(acc[11][0], w, v0.x); FFMA2(acc[11][1], w, v0.y);
                    FFMA2(acc[11][2], w, v1.x); FFMA2(acc[11][3], w, v1.y);
                    PACK2(w, pd.x);
                    FFMA2(acc[12][0], w, v0.x); FFMA2(acc[12][1], w, v0.y);
                    FFMA2(acc[12][2], w, v1.x); FFMA2(acc[12][3], w, v1.y);
                    PACK2(w, pd.y);
                    FFMA2(acc[13][0], w, v0.x); FFMA2(acc[13][1], w, v0.y);
                    FFMA2(acc[13][2], w, v1.x); FFMA2(acc[13][3], w, v1.y);
                    PACK2(w, pd.z);
                    FFMA2(acc[14][0], w, v0.x); FFMA2(acc[14][1], w, v0.y);
                    FFMA2(acc[14][2], w, v1.x); FFMA2(acc[14][3], w, v1.y);
                    PACK2(w, pd.w);
                    FFMA2(acc[15][0], w, v0.x); FFMA2(acc[15][1], w, v0.y);
                    FFMA2(acc[15][2], w, v1.x); FFMA2(acc[15][3], w, v1.y);
                }
                __syncwarp();
            }
        }

        // reduce denominators once per tile
#pragma unroll
        for (int ri = 0; ri < 16; ri++) {
            float s = l[ri];
#pragma unroll
            for (int o = 16; o > 0; o >>= 1)
                s += __shfl_xor_sync(0xffffffffu, s, o);
            l[ri] = s;
        }

        // head-2 warps publish lambda/l2-scaled contributions to ex (64x256)
        if (h == 1) {
#pragma unroll
            for (int ri = 0; ri < 16; ri++) {
                const int row = r0 + ri;
                float i2 = lamv / l[ri];
                float* exr = ex + row * 256;
                float p0, p1, p2, p3;
                UNPACK2(p0, p1, acc[ri][0]); UNPACK2(p2, p3, acc[ri][1]);
                *(float4*)(exr + lane * 4) =
                    make_float4(p0 * i2, p1 * i2, p2 * i2, p3 * i2);
                UNPACK2(p0, p1, acc[ri][2]); UNPACK2(p2, p3, acc[ri][3]);
                *(float4*)(exr + 128 + lane * 4) =
                    make_float4(p0 * i2, p1 * i2, p2 * i2, p3 * i2);
            }
        }
        __syncthreads();

        // head-1 warps combine + LayerNorm + store
        if (h == 0) {
#pragma unroll
            for (int ri = 0; ri < 16; ri++) {
                const int row = r0 + ri;
                const int tg  = t0 + row;
                float i1 = 1.f / l[ri];
                const float* exr = ex + row * 256;
                float4 e0 = *(const float4*)(exr + lane * 4);
                float4 e1 = *(const float4*)(exr + 128 + lane * 4);
                float A[8];
                float p0, p1, p2, p3;
                UNPACK2(p0, p1, acc[ri][0]); UNPACK2(p2, p3, acc[ri][1]);
                A[0] = p0 * i1 - e0.x; A[1] = p1 * i1 - e0.y;
                A[2] = p2 * i1 - e0.z; A[3] = p3 * i1 - e0.w;
                UNPACK2(p0, p1, acc[ri][2]); UNPACK2(p2, p3, acc[ri][3]);
                A[4] = p0 * i1 - e1.x; A[5] = p1 * i1 - e1.y;
                A[6] = p2 * i1 - e1.z; A[7] = p3 * i1 - e1.w;

                float s = 0.f;
#pragma unroll
                for (int k = 0; k < 8; k++) s += A[k];
#pragma unroll
                for (int o = 16; o > 0; o >>= 1)
                    s += __shfl_xor_sync(0xffffffffu, s, o);
                float mu = s * (1.f / 256.f);

                float q = 0.f;
#pragma unroll
                for (int k = 0; k < 8; k++) q += (A[k] - mu) * (A[k] - mu);
#pragma unroll
                for (int o = 16; o > 0; o >>= 1)
                    q += __shfl_xor_sync(0xffffffffu, q, o);
                float var  = q * (1.f / 256.f);
                float rstd = rsqrtf(var + LN_EPS_F);

                float4 o0, o1;
                o0.x = (A[0] - mu) * rstd * g[0] + bt[0];
                o0.y = (A[1] - mu) * rstd * g[1] + bt[1];
                o0.z = (A[2] - mu) * rstd * g[2] + bt[2];
                o0.w = (A[3] - mu) * rstd * g[3] + bt[3];
                o1.x = (A[4] - mu) * rstd * g[4] + bt[4];
                o1.y = (A[5] - mu) * rstd * g[5] + bt[5];
                o1.z = (A[6] - mu) * rstd * g[6] + bt[6];
                o1.w = (A[7] - mu) * rstd * g[7] + bt[7];

                *(float4*)(out + (base + tg) * NO + lane * 4) = o0;
                *(float4*)(out + (base + tg) * NO + 128 + lane * 4) = o1;
            }
        }
    }
}

// ---------------------------------------------------------------------------
extern "C" void kernel_launch(void* const* d_in, const int* in_sizes, int n_in,
                              void* d_out, int out_size)
{
    const float* x   = (const float*)d_in[0];
    const float* Wq  = (const float*)d_in[1];
    const float* Wk  = (const float*)d_in[2];
    const float* Wv  = (const float*)d_in[3];
    const float* Wqs = (const float*)d_in[4];
    const float* Wks = (const float*)d_in[5];
    const float* Wvs = (const float*)d_in[6];
    const float* lq1 = (const float*)d_in[7];
    const float* lq2 = (const float*)d_in[8];
    const float* lk1 = (const float*)d_in[9];
    const float* lk2 = (const float*)d_in[10];
    const float* gam = (const float*)d_in[11];
    const float* bet = (const float*)d_in[12];

    qkv_gemm<<<dim3(6, 128), 256>>>(x, Wq, Wk, Wv);
    state_fixup<<<64, 256>>>(x, Wqs, Wks, Wvs);
    lambda_kernel<<<1, 32>>>(lq1, lq2, lk1, lk2);

    const int smem_bytes = SM_TOTAL_F4 * (int)sizeof(float4);   // 218112
    cudaFuncSetAttribute(attn_kernel,
                         cudaFuncAttributeMaxDynamicSharedMemorySize, smem_bytes);
    attn_kernel<<<dim3(32, BB), 256, smem_bytes>>>((float*)d_out, gam, bet);
}

// round 11
// speedup vs baseline: 1.4379x; 1.4379x over previous
#include <cuda_runtime.h>
#include <math.h>
#include <stdint.h>

#define BB 4
#define TT 4096
#define DD 1024
#define NO 256      // 2*dv
#define NROW (BB*TT)
#define LN_EPS_F 1e-5f
#define LAMBDA_INIT 0.3555090675909693f
#define ATT_SCALE 0.0883883476483184405f   // 1/sqrt(128)

typedef unsigned long long u64;

// packed f32x2 helpers (sm_100+ PTX; SASS FFMA2/FADD2)
#define FFMA2(d, a, b) asm("fma.rn.f32x2 %0, %1, %2, %0;" : "+l"(d) : "l"(a), "l"(b))
#define PACK2(d, x)    asm("mov.b64 %0, {%1, %1};" : "=l"(d) : "r"(__float_as_uint(x)))
#define UNPACK2(lo, hi, v) do { unsigned _ul, _uh; \
    asm("mov.b64 {%0, %1}, %2;" : "=r"(_ul), "=r"(_uh) : "l"(v)); \
    (lo) = __uint_as_float(_ul); (hi) = __uint_as_float(_uh); } while (0)

// scratch (device globals: allocation-free rule)
__device__ float g_Q[NROW * NO];
__device__ float g_K[NROW * NO];
__device__ float g_V[NROW * NO];
__device__ float g_P1[67108864];     // [NROW][TT] exp-scores head 1
__device__ float g_P2[67108864];     // [NROW][TT] exp-scores head 2
__device__ float g_Lp[NROW * 64];    // per-(row, keytile, head) partial sums
__device__ float g_Winv[NROW * 2];   // (1/l1, lambda/l2) per row
__device__ float g_lambda;

// ---------------------------------------------------------------------------
// Kernel 1: uniform QKV GEMM (proven round-7 version, unchanged).
// ---------------------------------------------------------------------------
__global__ __launch_bounds__(256) void qkv_gemm(
    const float* __restrict__ x,
    const float* __restrict__ Wq,
    const float* __restrict__ Wk,
    const float* __restrict__ Wv)
{
    __shared__ float Xs[16][132];
    __shared__ float Ws[16][128];

    const int nt  = blockIdx.x;
    const int mt  = blockIdx.y;
    const int mat = nt >> 1;
    const int n0  = (nt & 1) * 128;
    const float* W = (mat == 0) ? Wq : ((mat == 1) ? Wk : Wv);
    float* Out     = (mat == 0) ? g_Q : ((mat == 1) ? g_K : g_V);

    const int m0  = mt * 128;
    const int tid = threadIdx.x;
    const int tx  = tid & 15;
    const int ty  = tid >> 4;

    const int xrow = tid >> 2;
    const int xkc  = tid & 3;
    const int wkr  = tid >> 5;
    const int wnc  = tid & 31;

    const float* xp0 = x + (size_t)(m0 + xrow) * DD + xkc * 4;
    const float* xp1 = x + (size_t)(m0 + xrow + 64) * DD + xkc * 4;
    const float* wp0 = W + (size_t)wkr * NO + n0 + wnc * 4;
    const float* wp1 = W + (size_t)(wkr + 8) * NO + n0 + wnc * 4;

    u64 c[4][8];
#pragma unroll
    for (int i = 0; i < 4; i++)
#pragma unroll
        for (int j = 0; j < 8; j++) c[i][j] = 0ull;

    float4 xr0 = *(const float4*)xp0;
    float4 xr1 = *(const float4*)xp1;
    float4 wr0 = *(const float4*)wp0;
    float4 wr1 = *(const float4*)wp1;

    for (int k0 = 0; k0 < DD; k0 += 16) {
        Xs[xkc * 4 + 0][xrow]      = xr0.x;
        Xs[xkc * 4 + 1][xrow]      = xr0.y;
        Xs[xkc * 4 + 2][xrow]      = xr0.z;
        Xs[xkc * 4 + 3][xrow]      = xr0.w;
        Xs[xkc * 4 + 0][xrow + 64] = xr1.x;
        Xs[xkc * 4 + 1][xrow + 64] = xr1.y;
        Xs[xkc * 4 + 2][xrow + 64] = xr1.z;
        Xs[xkc * 4 + 3][xrow + 64] = xr1.w;
        *(float4*)(&Ws[wkr][wnc * 4])     = wr0;
        *(float4*)(&Ws[wkr + 8][wnc * 4]) = wr1;
        __syncthreads();

        if (k0 + 16 < DD) {
            xr0 = *(const float4*)(xp0 + k0 + 16);
            xr1 = *(const float4*)(xp1 + k0 + 16);
            wr0 = *(const float4*)(wp0 + (size_t)(k0 + 16) * NO);
            wr1 = *(const float4*)(wp1 + (size_t)(k0 + 16) * NO);
        }

#pragma unroll
        for (int kk = 0; kk < 16; kk++) {
            ulonglong2 A0 = *(const ulonglong2*)(&Xs[kk][ty * 4]);
            ulonglong2 A1 = *(const ulonglong2*)(&Xs[kk][64 + ty * 4]);
            float4 b0 = *(const float4*)(&Ws[kk][tx * 4]);
            float4 b1 = *(const float4*)(&Ws[kk][64 + tx * 4]);
            u64 B[8];
            PACK2(B[0], b0.x); PACK2(B[1], b0.y); PACK2(B[2], b0.z); PACK2(B[3], b0.w);
            PACK2(B[4], b1.x); PACK2(B[5], b1.y); PACK2(B[6], b1.z); PACK2(B[7], b1.w);
#pragma unroll
            for (int j = 0; j < 8; j++) {
                FFMA2(c[0][j], A0.x, B[j]);
                FFMA2(c[1][j], A0.y, B[j]);
                FFMA2(c[2][j], A1.x, B[j]);
                FFMA2(c[3][j], A1.y, B[j]);
            }
        }
        __syncthreads();
    }

#pragma unroll
    for (int rp = 0; rp < 4; rp++) {
        const int r = (rp < 2) ? (ty * 4 + rp * 2) : (64 + ty * 4 + (rp - 2) * 2);
        float lo[8], hi[8];
#pragma unroll
        for (int j = 0; j < 8; j++) UNPACK2(lo[j], hi[j], c[rp][j]);
        float* o0 = Out + (size_t)(m0 + r) * NO + n0;
        float* o1 = o0 + NO;
        *(float4*)(o0 + tx * 4)      = make_float4(lo[0], lo[1], lo[2], lo[3]);
        *(float4*)(o0 + 64 + tx * 4) = make_float4(lo[4], lo[5], lo[6], lo[7]);
        *(float4*)(o1 + tx * 4)      = make_float4(hi[0], hi[1], hi[2], hi[3]);
        *(float4*)(o1 + 64 + tx * 4) = make_float4(hi[4], hi[5], hi[6], hi[7]);
    }
}

// ---------------------------------------------------------------------------
// Kernel 2: recompute the 64 state rows with the *_state weights.
// ---------------------------------------------------------------------------
__global__ __launch_bounds__(256) void state_fixup(
    const float* __restrict__ x,
    const float* __restrict__ Wqs,
    const float* __restrict__ Wks,
    const float* __restrict__ Wvs)
{
    __shared__ float xs[DD];
    const int id = blockIdx.x;
    const int b  = id >> 4;
    const int i  = id & 15;
    const int t  = (i < 8) ? i : (TT - 16 + i);
    const size_t row = (size_t)b * TT + t;
    const int tid = threadIdx.x;

    for (int d = tid; d < DD; d += 256) xs[d] = x[row * DD + d];
    __syncthreads();

    float aq = 0.f, ak = 0.f, av = 0.f;
    const int n = tid;
#pragma unroll 4
    for (int d = 0; d < DD; d++) {
        float xv = xs[d];
        aq += xv * Wqs[(size_t)d * NO + n];
        ak += xv * Wks[(size_t)d * NO + n];
        av += xv * Wvs[(size_t)d * NO + n];
    }
    g_Q[row * NO + n] = aq;
    g_K[row * NO + n] = ak;
    g_V[row * NO + n] = av;
}

// ---------------------------------------------------------------------------
// Kernel 3: lambda scalar
// ---------------------------------------------------------------------------
__global__ void lambda_kernel(const float* __restrict__ lq1,
                              const float* __restrict__ lq2,
                              const float* __restrict__ lk1,
                              const float* __restrict__ lk2)
{
    int lane = threadIdx.x;
    float s1 = 0.f, s2 = 0.f;
    for (int i = lane; i < 128; i += 32) {
        s1 += lq1[i] * lk1[i];
        s2 += lq2[i] * lk2[i];
    }
#pragma unroll
    for (int o = 16; o > 0; o >>= 1) {
        s1 += __shfl_xor_sync(0xffffffffu, s1, o);
        s2 += __shfl_xor_sync(0xffffffffu, s2, o);
    }
    if (lane == 0) g_lambda = expf(s1) - expf(s2) + LAMBDA_INIT;
}

// ---------------------------------------------------------------------------
// Kernel 4 (A): score GEMM.  For each causal (rowtile 128, keytile 128):
// S = Q Kt (two 128-dim phases: head1 then head2, shared acc bank),
// epilogue: mask, exp, store P tile + per-row partial sums.
// ---------------------------------------------------------------------------
__global__ __launch_bounds__(256, 2) void score_kernel()
{
    __shared__ float Qs[16][132];
    __shared__ float Ks[16][132];

    const int b = blockIdx.y;
    const int t = blockIdx.x;
    int r = (int)((sqrtf(8.f * t + 1.f) - 1.f) * 0.5f);
    while ((r + 1) * (r + 2) / 2 <= t) r++;
    while (r * (r + 1) / 2 > t) r--;
    const int kt  = t - r * (r + 1) / 2;
    const int r0g = r * 128;
    const int k0g = kt * 128;
    const size_t rowb = (size_t)b * TT;

    const int tid = threadIdx.x;
    const int tx  = tid & 15;
    const int ty  = tid >> 4;

#pragma unroll 1
    for (int ph = 0; ph < 2; ph++) {
        u64 c[4][8];
#pragma unroll
        for (int i = 0; i < 4; i++)
#pragma unroll
            for (int j = 0; j < 8; j++) c[i][j] = 0ull;

        for (int ch = 0; ch < 8; ch++) {
            const int db = ph * 128 + ch * 16;
            __syncthreads();
#pragma unroll
            for (int i = 0; i < 2; i++) {
                int idx = tid + i * 256;
                int row = idx & 127;
                int dq  = idx >> 7;
                float4 qv = *(const float4*)(g_Q + (rowb + r0g + row) * NO + db + dq * 4);
                Qs[dq * 4 + 0][row] = qv.x * ATT_SCALE;
                Qs[dq * 4 + 1][row] = qv.y * ATT_SCALE;
                Qs[dq * 4 + 2][row] = qv.z * ATT_SCALE;
                Qs[dq * 4 + 3][row] = qv.w * ATT_SCALE;
                float4 kv = *(const float4*)(g_K + (rowb + k0g + row) * NO + db + dq * 4);
                Ks[dq * 4 + 0][row] = kv.x;
                Ks[dq * 4 + 1][row] = kv.y;
                Ks[dq * 4 + 2][row] = kv.z;
                Ks[dq * 4 + 3][row] = kv.w;
            }
            __syncthreads();

#pragma unroll
            for (int kk = 0; kk < 16; kk++) {
                ulonglong2 A0 = *(const ulonglong2*)(&Qs[kk][ty * 4]);
                ulonglong2 A1 = *(const ulonglong2*)(&Qs[kk][64 + ty * 4]);
                float4 b0 = *(const float4*)(&Ks[kk][tx * 4]);
                float4 b1 = *(const float4*)(&Ks[kk][64 + tx * 4]);
                u64 B[8];
                PACK2(B[0], b0.x); PACK2(B[1], b0.y); PACK2(B[2], b0.z); PACK2(B[3], b0.w);
                PACK2(B[4], b1.x); PACK2(B[5], b1.y); PACK2(B[6], b1.z); PACK2(B[7], b1.w);
#pragma unroll
                for (int j = 0; j < 8; j++) {
                    FFMA2(c[0][j], A0.x, B[j]);
                    FFMA2(c[1][j], A0.y, B[j]);
                    FFMA2(c[2][j], A1.x, B[j]);
                    FFMA2(c[3][j], A1.y, B[j]);
                }
            }
        }

        // epilogue: mask + exp + store P tile + row-sum partials
        float* Pout = ph ? g_P2 : g_P1;
#pragma unroll
        for (int rp = 0; rp < 4; rp++) {
            const int rl = (rp < 2) ? (ty * 4 + rp * 2) : (64 + ty * 4 + (rp - 2) * 2);
            float lo[8], hi[8];
#pragma unroll
            for (int j = 0; j < 8; j++) UNPACK2(lo[j], hi[j], c[rp][j]);

#pragma unroll
            for (int e = 0; e < 2; e++) {
                const int rg = r0g + rl + e;
                const float* v = e ? hi : lo;
                float p[8];
#pragma unroll
                for (int j = 0; j < 8; j++) {
                    int key = k0g + ((j < 4) ? (tx * 4 + j) : (64 + tx * 4 + j - 4));
                    p[j] = (key <= rg) ? __expf(v[j]) : 0.f;
                }
                float* Pp = Pout + (rowb + rg) * (size_t)TT + k0g;
                *(float4*)(Pp + tx * 4)      = make_float4(p[0], p[1], p[2], p[3]);
                *(float4*)(Pp + 64 + tx * 4) = make_float4(p[4], p[5], p[6], p[7]);
                float rs = p[0] + p[1] + p[2] + p[3] + p[4] + p[5] + p[6] + p[7];
                rs += __shfl_xor_sync(0xffffffffu, rs, 1);
                rs += __shfl_xor_sync(0xffffffffu, rs, 2);
                rs += __shfl_xor_sync(0xffffffffu, rs, 4);
                rs += __shfl_xor_sync(0xffffffffu, rs, 8);
                if (tx == 0)
                    g_Lp[(rowb + rg) * 64 + kt * 2 + ph] = rs;
            }
        }
    }
}

// ---------------------------------------------------------------------------
// Kernel 5 (R): reduce per-tile partials -> (1/l1, lambda/l2) per row.
// ---------------------------------------------------------------------------
__global__ __launch_bounds__(256) void reduce_l()
{
    const int row  = blockIdx.x * 8 + (threadIdx.x >> 5);
    const int lane = threadIdx.x & 31;
    const int rib  = row & (TT - 1);
    const int nk   = (rib >> 7) + 1;     // key tiles of 128 for this row

    float v1 = 0.f, v2 = 0.f;
    if (lane < nk) {
        v1 = g_Lp[(size_t)row * 64 + 2 * lane];
        v2 = g_Lp[(size_t)row * 64 + 2 * lane + 1];
    }
#pragma unroll
    for (int o = 16; o > 0; o >>= 1) {
        v1 += __shfl_xor_sync(0xffffffffu, v1, o);
        v2 += __shfl_xor_sync(0xffffffffu, v2, o);
    }
    if (lane == 0) {
        g_Winv[row * 2]     = 1.f / v1;
        g_Winv[row * 2 + 1] = g_lambda / v2;
    }
}

// ---------------------------------------------------------------------------
// Kernel 6 (B): PV GEMM.  W = i1*P1 - (lambda*i2)*P2 formed at staging.
// Out[64 rows x 128 dims] += W V, key chunks of 32.  Pair-balanced tiles
// (r, 63-r): 130 chunks/CTA uniform.  Writes UNNORMALIZED-combined att.
// ---------------------------------------------------------------------------
__global__ __launch_bounds__(256, 2) void pv_kernel(float* __restrict__ out)
{
    __shared__ float Ws[32][66];
    __shared__ float Vs[32][132];
    __shared__ float Wi2[128];

    const int b    = blockIdx.y;
    const int p    = blockIdx.x >> 1;
    const int n0   = (blockIdx.x & 1) * 128;
    const size_t rowb = (size_t)b * TT;

    const int tid = threadIdx.x;
    const int tx  = tid & 15;      // row group
    const int ty  = tid >> 4;      // dim group

#pragma unroll 1
    for (int pass = 0; pass < 2; pass++) {
        const int r   = pass ? (63 - p) : p;
        const int t0  = r * 64;
        const int nch = 2 * r + 2;

        __syncthreads();
        if (tid < 64) {
            float2 wv = *(const float2*)(g_Winv + (rowb + t0 + tid) * 2);
            Wi2[tid * 2]     = wv.x;
            Wi2[tid * 2 + 1] = wv.y;
        }

        u64 c[2][8];
#pragma unroll
        for (int i = 0; i < 2; i++)
#pragma unroll
            for (int j = 0; j < 8; j++) c[i][j] = 0ull;

        for (int ch = 0; ch < nch; ch++) {
            const int kb = ch * 32;
            __syncthreads();
            // stage W (64 rows x 32 keys), transposed, combined weights
#pragma unroll
            for (int i = 0; i < 2; i++) {
                int idx = tid + i * 256;
                int row = idx >> 3;
                int kq  = idx & 7;
                size_t po = (rowb + t0 + row) * (size_t)TT + kb + kq * 4;
                float4 p1 = *(const float4*)(g_P1 + po);
                float4 p2 = *(const float4*)(g_P2 + po);
                float i1  = Wi2[row * 2];
                float li2 = Wi2[row * 2 + 1];
                Ws[kq * 4 + 0][row] = p1.x * i1 - p2.x * li2;
                Ws[kq * 4 + 1][row] = p1.y * i1 - p2.y * li2;
                Ws[kq * 4 + 2][row] = p1.z * i1 - p2.z * li2;
                Ws[kq * 4 + 3][row] = p1.w * i1 - p2.w * li2;
            }
            // stage V (32 keys x 128 dims)
#pragma unroll
            for (int i = 0; i < 4; i++) {
                int idx = tid + i * 256;
                int key = idx >> 5;
                int dq  = idx & 31;
                *(float4*)(&Vs[key][dq * 4]) =
                    *(const float4*)(g_V + (rowb + kb + key) * NO + n0 + dq * 4);
            }
            __syncthreads();

#pragma unroll 4
            for (int kk = 0; kk < 32; kk++) {
                u64 aLo = *(const u64*)(&Ws[kk][tx * 4]);
                u64 aHi = *(const u64*)(&Ws[kk][tx * 4 + 2]);
                float4 b0 = *(const float4*)(&Vs[kk][ty * 8]);
                float4 b1 = *(const float4*)(&Vs[kk][ty * 8 + 4]);
                u64 B[8];
                PACK2(B[0], b0.x); PACK2(B[1], b0.y); PACK2(B[2], b0.z); PACK2(B[3], b0.w);
                PACK2(B[4], b1.x); PACK2(B[5], b1.y); PACK2(B[6], b1.z); PACK2(B[7], b1.w);
#pragma unroll
                for (int j = 0; j < 8; j++) {
                    FFMA2(c[0][j], aLo, B[j]);
                    FFMA2(c[1][j], aHi, B[j]);
                }
            }
        }

        // epilogue: store combined attention (pre-LayerNorm)
#pragma unroll
        for (int rp = 0; rp < 2; rp++) {
            float lo[8], hi[8];
#pragma unroll
            for (int j = 0; j < 8; j++) UNPACK2(lo[j], hi[j], c[rp][j]);
            float* o0 = out + (rowb + t0 + tx * 4 + 2 * rp) * NO + n0 + ty * 8;
            float* o1 = o0 + NO;
            *(float4*)(o0)     = make_float4(lo[0], lo[1], lo[2], lo[3]);
            *(float4*)(o0 + 4) = make_float4(lo[4], lo[5], lo[6], lo[7]);
            *(float4*)(o1)     = make_float4(hi[0], hi[1], hi[2], hi[3]);
            *(float4*)(o1 + 4) = make_float4(hi[4], hi[5], hi[6], hi[7]);
        }
    }
}

// ---------------------------------------------------------------------------
// Kernel 7 (LN): row LayerNorm in-place on out.  1 warp per row.
// ---------------------------------------------------------------------------
__global__ __launch_bounds__(256) void ln_kernel(
    float* __restrict__ out,
    const float* __restrict__ ln_gamma,
    const float* __restrict__ ln_beta)
{
    const int row  = blockIdx.x * 8 + (threadIdx.x >> 5);
    const int lane = threadIdx.x & 31;
    float* rp = out + (size_t)row * NO;

    float4 a0 = *(const float4*)(rp + lane * 4);
    float4 a1 = *(const float4*)(rp + 128 + lane * 4);

    float s = a0.x + a0.y + a0.z + a0.w + a1.x + a1.y + a1.z + a1.w;
#pragma unroll
    for (int o = 16; o > 0; o >>= 1) s += __shfl_xor_sync(0xffffffffu, s, o);
    float mu = s * (1.f / 256.f);

    float q = 0.f;
    q += (a0.x - mu) * (a0.x - mu); q += (a0.y - mu) * (a0.y - mu);
    q += (a0.z - mu) * (a0.z - mu); q += (a0.w - mu) * (a0.w - mu);
    q += (a1.x - mu) * (a1.x - mu); q += (a1.y - mu) * (a1.y - mu);
    q += (a1.z - mu) * (a1.z - mu); q += (a1.w - mu) * (a1.w - mu);
#pragma unroll
    for (int o = 16; o > 0; o >>= 1) q += __shfl_xor_sync(0xffffffffu, q, o);
    float rstd = rsqrtf(q * (1.f / 256.f) + LN_EPS_F);

    float4 g0 = *(const float4*)(ln_gamma + lane * 4);
    float4 g1 = *(const float4*)(ln_gamma + 128 + lane * 4);
    float4 b0 = *(const float4*)(ln_beta + lane * 4);
    float4 b1 = *(const float4*)(ln_beta + 128 + lane * 4);

    float4 o0, o1;
    o0.x = (a0.x - mu) * rstd * g0.x + b0.x;
    o0.y = (a0.y - mu) * rstd * g0.y + b0.y;
    o0.z = (a0.z - mu) * rstd * g0.z + b0.z;
    o0.w = (a0.w - mu) * rstd * g0.w + b0.w;
    o1.x = (a1.x - mu) * rstd * g1.x + b1.x;
    o1.y = (a1.y - mu) * rstd * g1.y + b1.y;
    o1.z = (a1.z - mu) * rstd * g1.z + b1.z;
    o1.w = (a1.w - mu) * rstd * g1.w + b1.w;

    *(float4*)(rp + lane * 4) = o0;
    *(float4*)(rp + 128 + lane * 4) = o1;
}

// ---------------------------------------------------------------------------
extern "C" void kernel_launch(void* const* d_in, const int* in_sizes, int n_in,
                              void* d_out, int out_size)
{
    const float* x   = (const float*)d_in[0];
    const float* Wq  = (const float*)d_in[1];
    const float* Wk  = (const float*)d_in[2];
    const float* Wv  = (const float*)d_in[3];
    const float* Wqs = (const float*)d_in[4];
    const float* Wks = (const float*)d_in[5];
    const float* Wvs = (const float*)d_in[6];
    const float* lq1 = (const float*)d_in[7];
    const float* lq2 = (const float*)d_in[8];
    const float* lk1 = (const float*)d_in[9];
    const float* lk2 = (const float*)d_in[10];
    const float* gam = (const float*)d_in[11];
    const float* bet = (const float*)d_in[12];

    qkv_gemm<<<dim3(6, 128), 256>>>(x, Wq, Wk, Wv);
    state_fixup<<<64, 256>>>(x, Wqs, Wks, Wvs);
    lambda_kernel<<<1, 32>>>(lq1, lq2, lk1, lk2);

    score_kernel<<<dim3(528, BB), 256>>>();
    reduce_l<<<NROW / 8, 256>>>();
    pv_kernel<<<dim3(64, BB), 256>>>((float*)d_out);
    ln_kernel<<<NROW / 8, 256>>>((float*)d_out, gam, bet);
}

// round 12
// speedup vs baseline: 1.6074x; 1.1179x over previous
#include <cuda_runtime.h>
#include <math.h>
#include <stdint.h>

#define BB 4
#define TT 4096
#define DD 1024
#define NO 256      // 2*dv
#define NROW (BB*TT)
#define LN_EPS_F 1e-5f
#define LAMBDA_INIT 0.3555090675909693f
#define ATT_SCALE 0.0883883476483184405f   // 1/sqrt(128)

typedef unsigned long long u64;

// packed f32x2 helpers (sm_100+ PTX; SASS FFMA2/FADD2)
#define FFMA2(d, a, b) asm("fma.rn.f32x2 %0, %1, %2, %0;" : "+l"(d) : "l"(a), "l"(b))
#define PACK2(d, x)    asm("mov.b64 %0, {%1, %1};" : "=l"(d) : "r"(__float_as_uint(x)))
#define UNPACK2(lo, hi, v) do { unsigned _ul, _uh; \
    asm("mov.b64 {%0, %1}, %2;" : "=r"(_ul), "=r"(_uh) : "l"(v)); \
    (lo) = __uint_as_float(_ul); (hi) = __uint_as_float(_uh); } while (0)

// scratch (device globals: allocation-free rule)
__device__ float g_Q[NROW * NO];
__device__ float g_K[NROW * NO];
__device__ float g_V[NROW * NO];
__device__ float g_P1[67108864];     // [NROW][TT] exp-scores head 1
__device__ float g_P2[67108864];     // [NROW][TT] exp-scores head 2
__device__ float g_Lp[NROW * 64];    // per-(row, keytile, head) partial sums
__device__ float g_Winv[NROW * 2];   // (1/l1, lambda/l2) per row
__device__ float g_lambda;

// ---------------------------------------------------------------------------
// Kernel 1: uniform QKV GEMM (proven round-7 version, unchanged).
// ---------------------------------------------------------------------------
__global__ __launch_bounds__(256) void qkv_gemm(
    const float* __restrict__ x,
    const float* __restrict__ Wq,
    const float* __restrict__ Wk,
    const float* __restrict__ Wv)
{
    __shared__ float Xs[16][132];
    __shared__ float Ws[16][128];

    const int nt  = blockIdx.x;
    const int mt  = blockIdx.y;
    const int mat = nt >> 1;
    const int n0  = (nt & 1) * 128;
    const float* W = (mat == 0) ? Wq : ((mat == 1) ? Wk : Wv);
    float* Out     = (mat == 0) ? g_Q : ((mat == 1) ? g_K : g_V);

    const int m0  = mt * 128;
    const int tid = threadIdx.x;
    const int tx  = tid & 15;
    const int ty  = tid >> 4;

    const int xrow = tid >> 2;
    const int xkc  = tid & 3;
    const int wkr  = tid >> 5;
    const int wnc  = tid & 31;

    const float* xp0 = x + (size_t)(m0 + xrow) * DD + xkc * 4;
    const float* xp1 = x + (size_t)(m0 + xrow + 64) * DD + xkc * 4;
    const float* wp0 = W + (size_t)wkr * NO + n0 + wnc * 4;
    const float* wp1 = W + (size_t)(wkr + 8) * NO + n0 + wnc * 4;

    u64 c[4][8];
#pragma unroll
    for (int i = 0; i < 4; i++)
#pragma unroll
        for (int j = 0; j < 8; j++) c[i][j] = 0ull;

    float4 xr0 = *(const float4*)xp0;
    float4 xr1 = *(const float4*)xp1;
    float4 wr0 = *(const float4*)wp0;
    float4 wr1 = *(const float4*)wp1;

    for (int k0 = 0; k0 < DD; k0 += 16) {
        Xs[xkc * 4 + 0][xrow]      = xr0.x;
        Xs[xkc * 4 + 1][xrow]      = xr0.y;
        Xs[xkc * 4 + 2][xrow]      = xr0.z;
        Xs[xkc * 4 + 3][xrow]      = xr0.w;
        Xs[xkc * 4 + 0][xrow + 64] = xr1.x;
        Xs[xkc * 4 + 1][xrow + 64] = xr1.y;
        Xs[xkc * 4 + 2][xrow + 64] = xr1.z;
        Xs[xkc * 4 + 3][xrow + 64] = xr1.w;
        *(float4*)(&Ws[wkr][wnc * 4])     = wr0;
        *(float4*)(&Ws[wkr + 8][wnc * 4]) = wr1;
        __syncthreads();

        if (k0 + 16 < DD) {
            xr0 = *(const float4*)(xp0 + k0 + 16);
            xr1 = *(const float4*)(xp1 + k0 + 16);
            wr0 = *(const float4*)(wp0 + (size_t)(k0 + 16) * NO);
            wr1 = *(const float4*)(wp1 + (size_t)(k0 + 16) * NO);
        }

#pragma unroll
        for (int kk = 0; kk < 16; kk++) {
            ulonglong2 A0 = *(const ulonglong2*)(&Xs[kk][ty * 4]);
            ulonglong2 A1 = *(const ulonglong2*)(&Xs[kk][64 + ty * 4]);
            float4 b0 = *(const float4*)(&Ws[kk][tx * 4]);
            float4 b1 = *(const float4*)(&Ws[kk][64 + tx * 4]);
            u64 B[8];
            PACK2(B[0], b0.x); PACK2(B[1], b0.y); PACK2(B[2], b0.z); PACK2(B[3], b0.w);
            PACK2(B[4], b1.x); PACK2(B[5], b1.y); PACK2(B[6], b1.z); PACK2(B[7], b1.w);
#pragma unroll
            for (int j = 0; j < 8; j++) {
                FFMA2(c[0][j], A0.x, B[j]);
                FFMA2(c[1][j], A0.y, B[j]);
                FFMA2(c[2][j], A1.x, B[j]);
                FFMA2(c[3][j], A1.y, B[j]);
            }
        }
        __syncthreads();
    }

#pragma unroll
    for (int rp = 0; rp < 4; rp++) {
        const int r = (rp < 2) ? (ty * 4 + rp * 2) : (64 + ty * 4 + (rp - 2) * 2);
        float lo[8], hi[8];
#pragma unroll
        for (int j = 0; j < 8; j++) UNPACK2(lo[j], hi[j], c[rp][j]);
        float* o0 = Out + (size_t)(m0 + r) * NO + n0;
        float* o1 = o0 + NO;
        *(float4*)(o0 + tx * 4)      = make_float4(lo[0], lo[1], lo[2], lo[3]);
        *(float4*)(o0 + 64 + tx * 4) = make_float4(lo[4], lo[5], lo[6], lo[7]);
        *(float4*)(o1 + tx * 4)      = make_float4(hi[0], hi[1], hi[2], hi[3]);
        *(float4*)(o1 + 64 + tx * 4) = make_float4(hi[4], hi[5], hi[6], hi[7]);
    }
}

// ---------------------------------------------------------------------------
// Kernel 2: recompute the 64 state rows with the *_state weights.
// ---------------------------------------------------------------------------
__global__ __launch_bounds__(256) void state_fixup(
    const float* __restrict__ x,
    const float* __restrict__ Wqs,
    const float* __restrict__ Wks,
    const float* __restrict__ Wvs)
{
    __shared__ float xs[DD];
    const int id = blockIdx.x;
    const int b  = id >> 4;
    const int i  = id & 15;
    const int t  = (i < 8) ? i : (TT - 16 + i);
    const size_t row = (size_t)b * TT + t;
    const int tid = threadIdx.x;

    for (int d = tid; d < DD; d += 256) xs[d] = x[row * DD + d];
    __syncthreads();

    float aq = 0.f, ak = 0.f, av = 0.f;
    const int n = tid;
#pragma unroll 4
    for (int d = 0; d < DD; d++) {
        float xv = xs[d];
        aq += xv * Wqs[(size_t)d * NO + n];
        ak += xv * Wks[(size_t)d * NO + n];
        av += xv * Wvs[(size_t)d * NO + n];
    }
    g_Q[row * NO + n] = aq;
    g_K[row * NO + n] = ak;
    g_V[row * NO + n] = av;
}

// ---------------------------------------------------------------------------
// Kernel 3: lambda scalar
// ---------------------------------------------------------------------------
__global__ void lambda_kernel(const float* __restrict__ lq1,
                              const float* __restrict__ lq2,
                              const float* __restrict__ lk1,
                              const float* __restrict__ lk2)
{
    int lane = threadIdx.x;
    float s1 = 0.f, s2 = 0.f;
    for (int i = lane; i < 128; i += 32) {
        s1 += lq1[i] * lk1[i];
        s2 += lq2[i] * lk2[i];
    }
#pragma unroll
    for (int o = 16; o > 0; o >>= 1) {
        s1 += __shfl_xor_sync(0xffffffffu, s1, o);
        s2 += __shfl_xor_sync(0xffffffffu, s2, o);
    }
    if (lane == 0) g_lambda = expf(s1) - expf(s2) + LAMBDA_INIT;
}

// ---------------------------------------------------------------------------
// Kernel 4 (A): score GEMM with coalesced staging + register double-buffer.
// For each causal (rowtile 128, keytile 128): S = Q Kt, two 128-dim phases
// (head1, head2) flattened into 16 k-chunks of 16; epilogue (mask, exp,
// store P + row-sum partials) inlined at chunk 7 / 15.
// ---------------------------------------------------------------------------
__global__ __launch_bounds__(256, 2) void score_kernel()
{
    __shared__ float Qs[16][132];
    __shared__ float Ks[16][132];

    const int b = blockIdx.y;
    const int t = blockIdx.x;
    int r = (int)((sqrtf(8.f * t + 1.f) - 1.f) * 0.5f);
    while ((r + 1) * (r + 2) / 2 <= t) r++;
    while (r * (r + 1) / 2 > t) r--;
    const int kt  = t - r * (r + 1) / 2;
    const int r0g = r * 128;
    const int k0g = kt * 128;
    const size_t rowb = (size_t)b * TT;

    const int tid = threadIdx.x;
    const int tx  = tid & 15;
    const int ty  = tid >> 4;
    const int sdq = tid & 3;        // staging: k-quad within chunk
    const int sr0 = tid >> 2;       // staging: row (0..63; +64 for i=1)

    const float* qb0 = g_Q + (rowb + r0g + sr0) * NO + sdq * 4;
    const float* qb1 = qb0 + (size_t)64 * NO;
    const float* kb0 = g_K + (rowb + k0g + sr0) * NO + sdq * 4;
    const float* kb1 = kb0 + (size_t)64 * NO;

    float4 pq[2], pk[2];
#define SLOADG(g) do { \
        int db_ = (((g) >> 3) * 128) + (((g) & 7) * 16); \
        pq[0] = *(const float4*)(qb0 + db_); \
        pq[1] = *(const float4*)(qb1 + db_); \
        pk[0] = *(const float4*)(kb0 + db_); \
        pk[1] = *(const float4*)(kb1 + db_); \
    } while (0)

    u64 c[4][8];
#pragma unroll
    for (int i = 0; i < 4; i++)
#pragma unroll
        for (int j = 0; j < 8; j++) c[i][j] = 0ull;

    SLOADG(0);

    for (int g = 0; g < 16; g++) {
        __syncthreads();
#pragma unroll
        for (int i = 0; i < 2; i++) {
            int row = sr0 + i * 64;
            Qs[sdq * 4 + 0][row] = pq[i].x * ATT_SCALE;
            Qs[sdq * 4 + 1][row] = pq[i].y * ATT_SCALE;
            Qs[sdq * 4 + 2][row] = pq[i].z * ATT_SCALE;
            Qs[sdq * 4 + 3][row] = pq[i].w * ATT_SCALE;
            Ks[sdq * 4 + 0][row] = pk[i].x;
            Ks[sdq * 4 + 1][row] = pk[i].y;
            Ks[sdq * 4 + 2][row] = pk[i].z;
            Ks[sdq * 4 + 3][row] = pk[i].w;
        }
        __syncthreads();
        if (g < 15) SLOADG(g + 1);

#pragma unroll
        for (int kk = 0; kk < 16; kk++) {
            ulonglong2 A0 = *(const ulonglong2*)(&Qs[kk][ty * 4]);
            ulonglong2 A1 = *(const ulonglong2*)(&Qs[kk][64 + ty * 4]);
            float4 b0 = *(const float4*)(&Ks[kk][tx * 4]);
            float4 b1 = *(const float4*)(&Ks[kk][64 + tx * 4]);
            u64 B[8];
            PACK2(B[0], b0.x); PACK2(B[1], b0.y); PACK2(B[2], b0.z); PACK2(B[3], b0.w);
            PACK2(B[4], b1.x); PACK2(B[5], b1.y); PACK2(B[6], b1.z); PACK2(B[7], b1.w);
#pragma unroll
            for (int j = 0; j < 8; j++) {
                FFMA2(c[0][j], A0.x, B[j]);
                FFMA2(c[1][j], A0.y, B[j]);
                FFMA2(c[2][j], A1.x, B[j]);
                FFMA2(c[3][j], A1.y, B[j]);
            }
        }

        if ((g & 7) == 7) {
            // epilogue for phase ph = g>>3: mask + exp + store P + partials
            const int ph = g >> 3;
            float* Pout = ph ? g_P2 : g_P1;
#pragma unroll
            for (int rp = 0; rp < 4; rp++) {
                const int rl = (rp < 2) ? (ty * 4 + rp * 2)
                                        : (64 + ty * 4 + (rp - 2) * 2);
                float lo[8], hi[8];
#pragma unroll
                for (int j = 0; j < 8; j++) UNPACK2(lo[j], hi[j], c[rp][j]);

#pragma unroll
                for (int e = 0; e < 2; e++) {
                    const int rg = r0g + rl + e;
                    const float* v = e ? hi : lo;
                    float p[8];
#pragma unroll
                    for (int j = 0; j < 8; j++) {
                        int key = k0g + ((j < 4) ? (tx * 4 + j)
                                                 : (64 + tx * 4 + j - 4));
                        p[j] = (key <= rg) ? __expf(v[j]) : 0.f;
                    }
                    float* Pp = Pout + (rowb + rg) * (size_t)TT + k0g;
                    *(float4*)(Pp + tx * 4)      = make_float4(p[0], p[1], p[2], p[3]);
                    *(float4*)(Pp + 64 + tx * 4) = make_float4(p[4], p[5], p[6], p[7]);
                    float rs = p[0] + p[1] + p[2] + p[3] + p[4] + p[5] + p[6] + p[7];
                    rs += __shfl_xor_sync(0xffffffffu, rs, 1);
                    rs += __shfl_xor_sync(0xffffffffu, rs, 2);
                    rs += __shfl_xor_sync(0xffffffffu, rs, 4);
                    rs += __shfl_xor_sync(0xffffffffu, rs, 8);
                    if (tx == 0)
                        g_Lp[(rowb + rg) * 64 + kt * 2 + ph] = rs;
                }
            }
            // reset accumulators for next phase
#pragma unroll
            for (int i = 0; i < 4; i++)
#pragma unroll
                for (int j = 0; j < 8; j++) c[i][j] = 0ull;
        }
    }
#undef SLOADG
}

// ---------------------------------------------------------------------------
// Kernel 5 (R): reduce per-tile partials -> (1/l1, lambda/l2) per row.
// ---------------------------------------------------------------------------
__global__ __launch_bounds__(256) void reduce_l()
{
    const int row  = blockIdx.x * 8 + (threadIdx.x >> 5);
    const int lane = threadIdx.x & 31;
    const int rib  = row & (TT - 1);
    const int nk   = (rib >> 7) + 1;

    float v1 = 0.f, v2 = 0.f;
    if (lane < nk) {
        v1 = g_Lp[(size_t)row * 64 + 2 * lane];
        v2 = g_Lp[(size_t)row * 64 + 2 * lane + 1];
    }
#pragma unroll
    for (int o = 16; o > 0; o >>= 1) {
        v1 += __shfl_xor_sync(0xffffffffu, v1, o);
        v2 += __shfl_xor_sync(0xffffffffu, v2, o);
    }
    if (lane == 0) {
        g_Winv[row * 2]     = 1.f / v1;
        g_Winv[row * 2 + 1] = g_lambda / v2;
    }
}

// ---------------------------------------------------------------------------
// Kernel 6 (B): PV GEMM with register double-buffer.
// W = i1*P1 - (lambda*i2)*P2 formed at staging.  Out[64 x 128] = W V,
// key chunks of 32.  Pair-balanced tiles (r, 63-r): 130 chunks/CTA uniform.
// ---------------------------------------------------------------------------
__global__ __launch_bounds__(256, 2) void pv_kernel(float* __restrict__ out)
{
    __shared__ float Ws[32][66];
    __shared__ float Vs[32][132];
    __shared__ float Wi2[128];

    const int b    = blockIdx.y;
    const int p    = blockIdx.x >> 1;
    const int n0   = (blockIdx.x & 1) * 128;
    const size_t rowb = (size_t)b * TT;

    const int tid = threadIdx.x;
    const int tx  = tid & 15;      // row group
    const int ty  = tid >> 4;      // dim group
    const int wr0 = tid >> 3;      // W staging row (0..31; +32 for i=1)
    const int wkq = tid & 7;       // W staging k-quad
    const int vk0 = tid >> 5;      // V staging key (0..7; +8,16,24)
    const int vdq = tid & 31;      // V staging dim-quad

    float4 pp1[2], pp2[2], pv4[4];

#pragma unroll 1
    for (int pass = 0; pass < 2; pass++) {
        const int r   = pass ? (63 - p) : p;
        const int t0  = r * 64;
        const int nch = 2 * r + 2;

#define PVLOAD(ch) do { \
            int kb_ = (ch) * 32; \
            size_t po0 = (rowb + t0 + wr0) * (size_t)TT + kb_ + wkq * 4; \
            size_t po1 = po0 + (size_t)32 * TT; \
            pp1[0] = *(const float4*)(g_P1 + po0); \
            pp1[1] = *(const float4*)(g_P1 + po1); \
            pp2[0] = *(const float4*)(g_P2 + po0); \
            pp2[1] = *(const float4*)(g_P2 + po1); \
            const float* vb_ = g_V + (rowb + kb_ + vk0) * NO + n0 + vdq * 4; \
            pv4[0] = *(const float4*)(vb_); \
            pv4[1] = *(const float4*)(vb_ + (size_t)8  * NO); \
            pv4[2] = *(const float4*)(vb_ + (size_t)16 * NO); \
            pv4[3] = *(const float4*)(vb_ + (size_t)24 * NO); \
        } while (0)

        __syncthreads();           // previous pass done with smem
        if (tid < 64) {
            float2 wv = *(const float2*)(g_Winv + (rowb + t0 + tid) * 2);
            Wi2[tid * 2]     = wv.x;
            Wi2[tid * 2 + 1] = wv.y;
        }
        PVLOAD(0);

        u64 c[2][8];
#pragma unroll
        for (int i = 0; i < 2; i++)
#pragma unroll
            for (int j = 0; j < 8; j++) c[i][j] = 0ull;

        __syncthreads();           // Wi2 visible

        for (int ch = 0; ch < nch; ch++) {
            // store prefetched chunk
#pragma unroll
            for (int i = 0; i < 2; i++) {
                int row = wr0 + i * 32;
                float i1  = Wi2[row * 2];
                float li2 = Wi2[row * 2 + 1];
                float4 p1 = pp1[i], p2 = pp2[i];
                Ws[wkq * 4 + 0][row] = p1.x * i1 - p2.x * li2;
                Ws[wkq * 4 + 1][row] = p1.y * i1 - p2.y * li2;
                Ws[wkq * 4 + 2][row] = p1.z * i1 - p2.z * li2;
                Ws[wkq * 4 + 3][row] = p1.w * i1 - p2.w * li2;
            }
#pragma unroll
            for (int i = 0; i < 4; i++)
                *(float4*)(&Vs[vk0 + i * 8][vdq * 4]) = pv4[i];
            __syncthreads();

            if (ch + 1 < nch) PVLOAD(ch + 1);

#pragma unroll 4
            for (int kk = 0; kk < 32; kk++) {
                u64 aLo = *(const u64*)(&Ws[kk][tx * 4]);
                u64 aHi = *(const u64*)(&Ws[kk][tx * 4 + 2]);
                float4 b0 = *(const float4*)(&Vs[kk][ty * 8]);
                float4 b1 = *(const float4*)(&Vs[kk][ty * 8 + 4]);
                u64 B[8];
                PACK2(B[0], b0.x); PACK2(B[1], b0.y); PACK2(B[2], b0.z); PACK2(B[3], b0.w);
                PACK2(B[4], b1.x); PACK2(B[5], b1.y); PACK2(B[6], b1.z); PACK2(B[7], b1.w);
#pragma unroll
                for (int j = 0; j < 8; j++) {
                    FFMA2(c[0][j], aLo, B[j]);
                    FFMA2(c[1][j], aHi, B[j]);
                }
            }
            __syncthreads();
        }
#undef PVLOAD

        // epilogue: store combined attention (pre-LayerNorm)
#pragma unroll
        for (int rp = 0; rp < 2; rp++) {
            float lo[8], hi[8];
#pragma unroll
            for (int j = 0; j < 8; j++) UNPACK2(lo[j], hi[j], c[rp][j]);
            float* o0 = out + (rowb + t0 + tx * 4 + 2 * rp) * NO + n0 + ty * 8;
            float* o1 = o0 + NO;
            *(float4*)(o0)     = make_float4(lo[0], lo[1], lo[2], lo[3]);
            *(float4*)(o0 + 4) = make_float4(lo[4], lo[5], lo[6], lo[7]);
            *(float4*)(o1)     = make_float4(hi[0], hi[1], hi[2], hi[3]);
            *(float4*)(o1 + 4) = make_float4(hi[4], hi[5], hi[6], hi[7]);
        }
    }
}

// ---------------------------------------------------------------------------
// Kernel 7 (LN): row LayerNorm in-place on out.  1 warp per row.
// ---------------------------------------------------------------------------
__global__ __launch_bounds__(256) void ln_kernel(
    float* __restrict__ out,
    const float* __restrict__ ln_gamma,
    const float* __restrict__ ln_beta)
{
    const int row  = blockIdx.x * 8 + (threadIdx.x >> 5);
    const int lane = threadIdx.x & 31;
    float* rp = out + (size_t)row * NO;

    float4 a0 = *(const float4*)(rp + lane * 4);
    float4 a1 = *(const float4*)(rp + 128 + lane * 4);

    float s = a0.x + a0.y + a0.z + a0.w + a1.x + a1.y + a1.z + a1.w;
#pragma unroll
    for (int o = 16; o > 0; o >>= 1) s += __shfl_xor_sync(0xffffffffu, s, o);
    float mu = s * (1.f / 256.f);

    float q = 0.f;
    q += (a0.x - mu) * (a0.x - mu); q += (a0.y - mu) * (a0.y - mu);
    q += (a0.z - mu) * (a0.z - mu); q += (a0.w - mu) * (a0.w - mu);
    q += (a1.x - mu) * (a1.x - mu); q += (a1.y - mu) * (a1.y - mu);
    q += (a1.z - mu) * (a1.z - mu); q += (a1.w - mu) * (a1.w - mu);
#pragma unroll
    for (int o = 16; o > 0; o >>= 1) q += __shfl_xor_sync(0xffffffffu, q, o);
    float rstd = rsqrtf(q * (1.f / 256.f) + LN_EPS_F);

    float4 g0 = *(const float4*)(ln_gamma + lane * 4);
    float4 g1 = *(const float4*)(ln_gamma + 128 + lane * 4);
    float4 b0 = *(const float4*)(ln_beta + lane * 4);
    float4 b1 = *(const float4*)(ln_beta + 128 + lane * 4);

    float4 o0, o1;
    o0.x = (a0.x - mu) * rstd * g0.x + b0.x;
    o0.y = (a0.y - mu) * rstd * g0.y + b0.y;
    o0.z = (a0.z - mu) * rstd * g0.z + b0.z;
    o0.w = (a0.w - mu) * rstd * g0.w + b0.w;
    o1.x = (a1.x - mu) * rstd * g1.x + b1.x;
    o1.y = (a1.y - mu) * rstd * g1.y + b1.y;
    o1.z = (a1.z - mu) * rstd * g1.z + b1.z;
    o1.w = (a1.w - mu) * rstd * g1.w + b1.w;

    *(float4*)(rp + lane * 4) = o0;
    *(float4*)(rp + 128 + lane * 4) = o1;
}

// ---------------------------------------------------------------------------
extern "C" void kernel_launch(void* const* d_in, const int* in_sizes, int n_in,
                              void* d_out, int out_size)
{
    const float* x   = (const float*)d_in[0];
    const float* Wq  = (const float*)d_in[1];
    const float* Wk  = (const float*)d_in[2];
    const float* Wv  = (const float*)d_in[3];
    const float* Wqs = (const float*)d_in[4];
    const float* Wks = (const float*)d_in[5];
    const float* Wvs = (const float*)d_in[6];
    const float* lq1 = (const float*)d_in[7];
    const float* lq2 = (const float*)d_in[8];
    const float* lk1 = (const float*)d_in[9];
    const float* lk2 = (const float*)d_in[10];
    const float* gam = (const float*)d_in[11];
    const float* bet = (const float*)d_in[12];

    qkv_gemm<<<dim3(6, 128), 256>>>(x, Wq, Wk, Wv);
    state_fixup<<<64, 256>>>(x, Wqs, Wks, Wvs);
    lambda_kernel<<<1, 32>>>(lq1, lq2, lk1, lk2);

    score_kernel<<<dim3(528, BB), 256>>>();
    reduce_l<<<NROW / 8, 256>>>();
    pv_kernel<<<dim3(64, BB), 256>>>((float*)d_out);
    ln_kernel<<<NROW / 8, 256>>>((float*)d_out, gam, bet);
}

// round 14
// speedup vs baseline: 1.6082x; 1.0005x over previous
#include <cuda_runtime.h>
#include <math.h>
#include <stdint.h>

#define BB 4
#define TT 4096
#define DD 1024
#define NO 256      // 2*dv
#define NROW (BB*TT)
#define LN_EPS_F 1e-5f
#define LAMBDA_INIT 0.3555090675909693f
#define ATT_SCALE 0.0883883476483184405f   // 1/sqrt(128)

typedef unsigned long long u64;

// packed f32x2 helpers (sm_100+ PTX; SASS FFMA2/FADD2)
#define FFMA2(d, a, b) asm("fma.rn.f32x2 %0, %1, %2, %0;" : "+l"(d) : "l"(a), "l"(b))
#define PACK2(d, x)    asm("mov.b64 %0, {%1, %1};" : "=l"(d) : "r"(__float_as_uint(x)))
#define UNPACK2(lo, hi, v) do { unsigned _ul, _uh; \
    asm("mov.b64 {%0, %1}, %2;" : "=r"(_ul), "=r"(_uh) : "l"(v)); \
    (lo) = __uint_as_float(_ul); (hi) = __uint_as_float(_uh); } while (0)

// scratch (device globals: allocation-free rule)
__device__ float g_Q[NROW * NO];
__device__ float g_K[NROW * NO];
__device__ float g_V[NROW * NO];
__device__ float g_P1[67108864];     // [NROW][TT] exp-scores head 1
__device__ float g_P2[67108864];     // [NROW][TT] exp-scores head 2
__device__ float g_Lp[NROW * 64];    // per-(row, keytile, head) partial sums
__device__ float g_Winv[NROW * 2];   // (1/l1, lambda/l2) per row
__device__ float g_lambda;

// ---------------------------------------------------------------------------
// Kernel 1: uniform QKV GEMM (proven round-7 version, unchanged).
// ---------------------------------------------------------------------------
__global__ __launch_bounds__(256) void qkv_gemm(
    const float* __restrict__ x,
    const float* __restrict__ Wq,
    const float* __restrict__ Wk,
    const float* __restrict__ Wv)
{
    __shared__ float Xs[16][132];
    __shared__ float Ws[16][128];

    const int nt  = blockIdx.x;
    const int mt  = blockIdx.y;
    const int mat = nt >> 1;
    const int n0  = (nt & 1) * 128;
    const float* W = (mat == 0) ? Wq : ((mat == 1) ? Wk : Wv);
    float* Out     = (mat == 0) ? g_Q : ((mat == 1) ? g_K : g_V);

    const int m0  = mt * 128;
    const int tid = threadIdx.x;
    const int tx  = tid & 15;
    const int ty  = tid >> 4;

    const int xrow = tid >> 2;
    const int xkc  = tid & 3;
    const int wkr  = tid >> 5;
    const int wnc  = tid & 31;

    const float* xp0 = x + (size_t)(m0 + xrow) * DD + xkc * 4;
    const float* xp1 = x + (size_t)(m0 + xrow + 64) * DD + xkc * 4;
    const float* wp0 = W + (size_t)wkr * NO + n0 + wnc * 4;
    const float* wp1 = W + (size_t)(wkr + 8) * NO + n0 + wnc * 4;

    u64 c[4][8];
#pragma unroll
    for (int i = 0; i < 4; i++)
#pragma unroll
        for (int j = 0; j < 8; j++) c[i][j] = 0ull;

    float4 xr0 = *(const float4*)xp0;
    float4 xr1 = *(const float4*)xp1;
    float4 wr0 = *(const float4*)wp0;
    float4 wr1 = *(const float4*)wp1;

    for (int k0 = 0; k0 < DD; k0 += 16) {
        Xs[xkc * 4 + 0][xrow]      = xr0.x;
        Xs[xkc * 4 + 1][xrow]      = xr0.y;
        Xs[xkc * 4 + 2][xrow]      = xr0.z;
        Xs[xkc * 4 + 3][xrow]      = xr0.w;
        Xs[xkc * 4 + 0][xrow + 64] = xr1.x;
        Xs[xkc * 4 + 1][xrow + 64] = xr1.y;
        Xs[xkc * 4 + 2][xrow + 64] = xr1.z;
        Xs[xkc * 4 + 3][xrow + 64] = xr1.w;
        *(float4*)(&Ws[wkr][wnc * 4])     = wr0;
        *(float4*)(&Ws[wkr + 8][wnc * 4]) = wr1;
        __syncthreads();

        if (k0 + 16 < DD) {
            xr0 = *(const float4*)(xp0 + k0 + 16);
            xr1 = *(const float4*)(xp1 + k0 + 16);
            wr0 = *(const float4*)(wp0 + (size_t)(k0 + 16) * NO);
            wr1 = *(const float4*)(wp1 + (size_t)(k0 + 16) * NO);
        }

#pragma unroll
        for (int kk = 0; kk < 16; kk++) {
            ulonglong2 A0 = *(const ulonglong2*)(&Xs[kk][ty * 4]);
            ulonglong2 A1 = *(const ulonglong2*)(&Xs[kk][64 + ty * 4]);
            float4 b0 = *(const float4*)(&Ws[kk][tx * 4]);
            float4 b1 = *(const float4*)(&Ws[kk][64 + tx * 4]);
            u64 B[8];
            PACK2(B[0], b0.x); PACK2(B[1], b0.y); PACK2(B[2], b0.z); PACK2(B[3], b0.w);
            PACK2(B[4], b1.x); PACK2(B[5], b1.y); PACK2(B[6], b1.z); PACK2(B[7], b1.w);
#pragma unroll
            for (int j = 0; j < 8; j++) {
                FFMA2(c[0][j], A0.x, B[j]);
                FFMA2(c[1][j], A0.y, B[j]);
                FFMA2(c[2][j], A1.x, B[j]);
                FFMA2(c[3][j], A1.y, B[j]);
            }
        }
        __syncthreads();
    }

#pragma unroll
    for (int rp = 0; rp < 4; rp++) {
        const int r = (rp < 2) ? (ty * 4 + rp * 2) : (64 + ty * 4 + (rp - 2) * 2);
        float lo[8], hi[8];
#pragma unroll
        for (int j = 0; j < 8; j++) UNPACK2(lo[j], hi[j], c[rp][j]);
        float* o0 = Out + (size_t)(m0 + r) * NO + n0;
        float* o1 = o0 + NO;
        *(float4*)(o0 + tx * 4)      = make_float4(lo[0], lo[1], lo[2], lo[3]);
        *(float4*)(o0 + 64 + tx * 4) = make_float4(lo[4], lo[5], lo[6], lo[7]);
        *(float4*)(o1 + tx * 4)      = make_float4(hi[0], hi[1], hi[2], hi[3]);
        *(float4*)(o1 + 64 + tx * 4) = make_float4(hi[4], hi[5], hi[6], hi[7]);
    }
}

// ---------------------------------------------------------------------------
// Kernel 2: recompute the 64 state rows with the *_state weights.
// ---------------------------------------------------------------------------
__global__ __launch_bounds__(256) void state_fixup(
    const float* __restrict__ x,
    const float* __restrict__ Wqs,
    const float* __restrict__ Wks,
    const float* __restrict__ Wvs)
{
    __shared__ float xs[DD];
    const int id = blockIdx.x;
    const int b  = id >> 4;
    const int i  = id & 15;
    const int t  = (i < 8) ? i : (TT - 16 + i);
    const size_t row = (size_t)b * TT + t;
    const int tid = threadIdx.x;

    for (int d = tid; d < DD; d += 256) xs[d] = x[row * DD + d];
    __syncthreads();

    float aq = 0.f, ak = 0.f, av = 0.f;
    const int n = tid;
#pragma unroll 4
    for (int d = 0; d < DD; d++) {
        float xv = xs[d];
        aq += xv * Wqs[(size_t)d * NO + n];
        ak += xv * Wks[(size_t)d * NO + n];
        av += xv * Wvs[(size_t)d * NO + n];
    }
    g_Q[row * NO + n] = aq;
    g_K[row * NO + n] = ak;
    g_V[row * NO + n] = av;
}

// ---------------------------------------------------------------------------
// Kernel 3: lambda scalar
// ---------------------------------------------------------------------------
__global__ void lambda_kernel(const float* __restrict__ lq1,
                              const float* __restrict__ lq2,
                              const float* __restrict__ lk1,
                              const float* __restrict__ lk2)
{
    int lane = threadIdx.x;
    float s1 = 0.f, s2 = 0.f;
    for (int i = lane; i < 128; i += 32) {
        s1 += lq1[i] * lk1[i];
        s2 += lq2[i] * lk2[i];
    }
#pragma unroll
    for (int o = 16; o > 0; o >>= 1) {
        s1 += __shfl_xor_sync(0xffffffffu, s1, o);
        s2 += __shfl_xor_sync(0xffffffffu, s2, o);
    }
    if (lane == 0) g_lambda = expf(s1) - expf(s2) + LAMBDA_INIT;
}

// ---------------------------------------------------------------------------
// Kernel 4 (A): score GEMM, coalesced staging + reg prefetch + smem
// DOUBLE-BUFFER (one barrier per chunk).  For each causal (rowtile 128,
// keytile 128): S = Q Kt, two 128-dim phases flattened into 16 k-chunks;
// epilogue (mask, exp, store P + partials) inlined at chunk 7 / 15.
// ---------------------------------------------------------------------------
__global__ __launch_bounds__(256, 2) void score_kernel()
{
    __shared__ float Qs[2][16][132];
    __shared__ float Ks[2][16][132];

    const int b = blockIdx.y;
    const int t = blockIdx.x;
    int r = (int)((sqrtf(8.f * t + 1.f) - 1.f) * 0.5f);
    while ((r + 1) * (r + 2) / 2 <= t) r++;
    while (r * (r + 1) / 2 > t) r--;
    const int kt  = t - r * (r + 1) / 2;
    const int r0g = r * 128;
    const int k0g = kt * 128;
    const size_t rowb = (size_t)b * TT;

    const int tid = threadIdx.x;
    const int tx  = tid & 15;
    const int ty  = tid >> 4;
    const int sdq = tid & 3;        // staging: k-quad within chunk
    const int sr0 = tid >> 2;       // staging: row (0..63; +64 for i=1)

    const float* qb0 = g_Q + (rowb + r0g + sr0) * NO + sdq * 4;
    const float* qb1 = qb0 + (size_t)64 * NO;
    const float* kb0 = g_K + (rowb + k0g + sr0) * NO + sdq * 4;
    const float* kb1 = kb0 + (size_t)64 * NO;

    float4 pq[2], pk[2];
#define SLOADG(g) do { \
        int db_ = (((g) >> 3) * 128) + (((g) & 7) * 16); \
        pq[0] = *(const float4*)(qb0 + db_); \
        pq[1] = *(const float4*)(qb1 + db_); \
        pk[0] = *(const float4*)(kb0 + db_); \
        pk[1] = *(const float4*)(kb1 + db_); \
    } while (0)

    u64 c[4][8];
#pragma unroll
    for (int i = 0; i < 4; i++)
#pragma unroll
        for (int j = 0; j < 8; j++) c[i][j] = 0ull;

    SLOADG(0);

    for (int g = 0; g < 16; g++) {
        const int bf = g & 1;
#pragma unroll
        for (int i = 0; i < 2; i++) {
            int row = sr0 + i * 64;
            Qs[bf][sdq * 4 + 0][row] = pq[i].x * ATT_SCALE;
            Qs[bf][sdq * 4 + 1][row] = pq[i].y * ATT_SCALE;
            Qs[bf][sdq * 4 + 2][row] = pq[i].z * ATT_SCALE;
            Qs[bf][sdq * 4 + 3][row] = pq[i].w * ATT_SCALE;
            Ks[bf][sdq * 4 + 0][row] = pk[i].x;
            Ks[bf][sdq * 4 + 1][row] = pk[i].y;
            Ks[bf][sdq * 4 + 2][row] = pk[i].z;
            Ks[bf][sdq * 4 + 3][row] = pk[i].w;
        }
        __syncthreads();
        if (g < 15) SLOADG(g + 1);

#pragma unroll
        for (int kk = 0; kk < 16; kk++) {
            ulonglong2 A0 = *(const ulonglong2*)(&Qs[bf][kk][ty * 4]);
            ulonglong2 A1 = *(const ulonglong2*)(&Qs[bf][kk][64 + ty * 4]);
            float4 b0 = *(const float4*)(&Ks[bf][kk][tx * 4]);
            float4 b1 = *(const float4*)(&Ks[bf][kk][64 + tx * 4]);
            u64 B[8];
            PACK2(B[0], b0.x); PACK2(B[1], b0.y); PACK2(B[2], b0.z); PACK2(B[3], b0.w);
            PACK2(B[4], b1.x); PACK2(B[5], b1.y); PACK2(B[6], b1.z); PACK2(B[7], b1.w);
#pragma unroll
            for (int j = 0; j < 8; j++) {
                FFMA2(c[0][j], A0.x, B[j]);
                FFMA2(c[1][j], A0.y, B[j]);
                FFMA2(c[2][j], A1.x, B[j]);
                FFMA2(c[3][j], A1.y, B[j]);
            }
        }

        if ((g & 7) == 7) {
            // epilogue for phase ph = g>>3: mask + exp + store P + partials
            const int ph = g >> 3;
            float* Pout = ph ? g_P2 : g_P1;
#pragma unroll
            for (int rp = 0; rp < 4; rp++) {
                const int rl = (rp < 2) ? (ty * 4 + rp * 2)
                                        : (64 + ty * 4 + (rp - 2) * 2);
                float lo[8], hi[8];
#pragma unroll
                for (int j = 0; j < 8; j++) UNPACK2(lo[j], hi[j], c[rp][j]);

#pragma unroll
                for (int e = 0; e < 2; e++) {
                    const int rg = r0g + rl + e;
                    const float* v = e ? hi : lo;
                    float p[8];
#pragma unroll
                    for (int j = 0; j < 8; j++) {
                        int key = k0g + ((j < 4) ? (tx * 4 + j)
                                                 : (64 + tx * 4 + j - 4));
                        p[j] = (key <= rg) ? __expf(v[j]) : 0.f;
                    }
                    float* Pp = Pout + (rowb + rg) * (size_t)TT + k0g;
                    *(float4*)(Pp + tx * 4)      = make_float4(p[0], p[1], p[2], p[3]);
                    *(float4*)(Pp + 64 + tx * 4) = make_float4(p[4], p[5], p[6], p[7]);
                    float rs = p[0] + p[1] + p[2] + p[3] + p[4] + p[5] + p[6] + p[7];
                    rs += __shfl_xor_sync(0xffffffffu, rs, 1);
                    rs += __shfl_xor_sync(0xffffffffu, rs, 2);
                    rs += __shfl_xor_sync(0xffffffffu, rs, 4);
                    rs += __shfl_xor_sync(0xffffffffu, rs, 8);
                    if (tx == 0)
                        g_Lp[(rowb + rg) * 64 + kt * 2 + ph] = rs;
                }
            }
#pragma unroll
            for (int i = 0; i < 4; i++)
#pragma unroll
                for (int j = 0; j < 8; j++) c[i][j] = 0ull;
        }
    }
#undef SLOADG
}

// ---------------------------------------------------------------------------
// Kernel 5 (R): reduce per-tile partials -> (1/l1, lambda/l2) per row.
// ---------------------------------------------------------------------------
__global__ __launch_bounds__(256) void reduce_l()
{
    const int row  = blockIdx.x * 8 + (threadIdx.x >> 5);
    const int lane = threadIdx.x & 31;
    const int rib  = row & (TT - 1);
    const int nk   = (rib >> 7) + 1;

    float v1 = 0.f, v2 = 0.f;
    if (lane < nk) {
        v1 = g_Lp[(size_t)row * 64 + 2 * lane];
        v2 = g_Lp[(size_t)row * 64 + 2 * lane + 1];
    }
#pragma unroll
    for (int o = 16; o > 0; o >>= 1) {
        v1 += __shfl_xor_sync(0xffffffffu, v1, o);
        v2 += __shfl_xor_sync(0xffffffffu, v2, o);
    }
    if (lane == 0) {
        g_Winv[row * 2]     = 1.f / v1;
        g_Winv[row * 2 + 1] = g_lambda / v2;
    }
}

// ---------------------------------------------------------------------------
// Kernel 6 (B): PV GEMM, 32 rows x 256 dims per tile (each P element read
// ONCE), reg prefetch + smem double-buffer (one barrier per chunk).
// W = i1*P1 - (lambda*i2)*P2 formed at staging.  Pair-balanced row-tiles
// (p, 127-p): 129 chunks/CTA uniform.  grid (64, BB) = 256 CTAs.
// Ws pad = 34 floats (136B rows) so u64 reads stay 8-byte aligned.
// ---------------------------------------------------------------------------
__global__ __launch_bounds__(256, 2) void pv_kernel(float* __restrict__ out)
{
    __shared__ float Ws[2][32][34];    // [buf][key][row] transposed W (8B-aligned rows)
    __shared__ float Vs[2][32][260];   // [buf][key][dim]
    __shared__ float Wi2[64];          // (i1, li2) per row

    const int b    = blockIdx.y;
    const int p    = blockIdx.x;       // 0..63
    const size_t rowb = (size_t)b * TT;

    const int tid = threadIdx.x;
    const int tx  = tid & 7;           // row group (4 rows)
    const int ty  = tid >> 3;          // dim group (8 dims)
    const int wr  = tid >> 3;          // W staging row (0..31)
    const int wkq = tid & 7;           // W staging k-quad

    float4 pp1, pp2, pv4[8];

#pragma unroll 1
    for (int pass = 0; pass < 2; pass++) {
        const int r   = pass ? (127 - p) : p;
        const int t0  = r * 32;
        const int nch = r + 1;

#define PVLOAD(ch) do { \
            int kb_ = (ch) * 32; \
            size_t po_ = (rowb + t0 + wr) * (size_t)TT + kb_ + wkq * 4; \
            pp1 = *(const float4*)(g_P1 + po_); \
            pp2 = *(const float4*)(g_P2 + po_); \
            _Pragma("unroll") \
            for (int i_ = 0; i_ < 8; i_++) { \
                int idx_ = tid + i_ * 256; \
                int key_ = idx_ >> 6; \
                int dq_  = idx_ & 63; \
                pv4[i_] = *(const float4*)(g_V + (rowb + kb_ + key_) * NO + dq_ * 4); \
            } \
        } while (0)

        __syncthreads();               // previous pass done with smem
        if (tid < 32) {
            float2 wv = *(const float2*)(g_Winv + (rowb + t0 + tid) * 2);
            Wi2[tid * 2]     = wv.x;
            Wi2[tid * 2 + 1] = wv.y;
        }
        PVLOAD(0);

        u64 c[2][8];
#pragma unroll
        for (int i = 0; i < 2; i++)
#pragma unroll
            for (int j = 0; j < 8; j++) c[i][j] = 0ull;

        __syncthreads();               // Wi2 visible

        for (int ch = 0; ch < nch; ch++) {
            const int bf = ch & 1;
            {
                float i1  = Wi2[wr * 2];
                float li2 = Wi2[wr * 2 + 1];
                Ws[bf][wkq * 4 + 0][wr] = pp1.x * i1 - pp2.x * li2;
                Ws[bf][wkq * 4 + 1][wr] = pp1.y * i1 - pp2.y * li2;
                Ws[bf][wkq * 4 + 2][wr] = pp1.z * i1 - pp2.z * li2;
                Ws[bf][wkq * 4 + 3][wr] = pp1.w * i1 - pp2.w * li2;
            }
#pragma unroll
            for (int i = 0; i < 8; i++) {
                int idx = tid + i * 256;
                int key = idx >> 6;
                int dq  = idx & 63;
                *(float4*)(&Vs[bf][key][dq * 4]) = pv4[i];
            }
            __syncthreads();

            if (ch + 1 < nch) PVLOAD(ch + 1);

#pragma unroll 4
            for (int kk = 0; kk < 32; kk++) {
                u64 aLo = *(const u64*)(&Ws[bf][kk][tx * 4]);
                u64 aHi = *(const u64*)(&Ws[bf][kk][tx * 4 + 2]);
                float4 b0 = *(const float4*)(&Vs[bf][kk][ty * 8]);
                float4 b1 = *(const float4*)(&Vs[bf][kk][ty * 8 + 4]);
                u64 B[8];
                PACK2(B[0], b0.x); PACK2(B[1], b0.y); PACK2(B[2], b0.z); PACK2(B[3], b0.w);
                PACK2(B[4], b1.x); PACK2(B[5], b1.y); PACK2(B[6], b1.z); PACK2(B[7], b1.w);
#pragma unroll
                for (int j = 0; j < 8; j++) {
                    FFMA2(c[0][j], aLo, B[j]);
                    FFMA2(c[1][j], aHi, B[j]);
                }
            }
        }
#undef PVLOAD

        // epilogue: store combined attention (pre-LayerNorm)
#pragma unroll
        for (int rp = 0; rp < 2; rp++) {
            float lo[8], hi[8];
#pragma unroll
            for (int j = 0; j < 8; j++) UNPACK2(lo[j], hi[j], c[rp][j]);
            float* o0 = out + (rowb + t0 + tx * 4 + 2 * rp) * NO + ty * 8;
            float* o1 = o0 + NO;
            *(float4*)(o0)     = make_float4(lo[0], lo[1], lo[2], lo[3]);
            *(float4*)(o0 + 4) = make_float4(lo[4], lo[5], lo[6], lo[7]);
            *(float4*)(o1)     = make_float4(hi[0], hi[1], hi[2], hi[3]);
            *(float4*)(o1 + 4) = make_float4(hi[4], hi[5], hi[6], hi[7]);
        }
    }
}

// ---------------------------------------------------------------------------
// Kernel 7 (LN): row LayerNorm in-place on out.  1 warp per row.
// ---------------------------------------------------------------------------
__global__ __launch_bounds__(256) void ln_kernel(
    float* __restrict__ out,
    const float* __restrict__ ln_gamma,
    const float* __restrict__ ln_beta)
{
    const int row  = blockIdx.x * 8 + (threadIdx.x >> 5);
    const int lane = threadIdx.x & 31;
    float* rp = out + (size_t)row * NO;

    float4 a0 = *(const float4*)(rp + lane * 4);
    float4 a1 = *(const float4*)(rp + 128 + lane * 4);

    float s = a0.x + a0.y + a0.z + a0.w + a1.x + a1.y + a1.z + a1.w;
#pragma unroll
    for (int o = 16; o > 0; o >>= 1) s += __shfl_xor_sync(0xffffffffu, s, o);
    float mu = s * (1.f / 256.f);

    float q = 0.f;
    q += (a0.x - mu) * (a0.x - mu); q += (a0.y - mu) * (a0.y - mu);
    q += (a0.z - mu) * (a0.z - mu); q += (a0.w - mu) * (a0.w - mu);
    q += (a1.x - mu) * (a1.x - mu); q += (a1.y - mu) * (a1.y - mu);
    q += (a1.z - mu) * (a1.z - mu); q += (a1.w - mu) * (a1.w - mu);
#pragma unroll
    for (int o = 16; o > 0; o >>= 1) q += __shfl_xor_sync(0xffffffffu, q, o);
    float rstd = rsqrtf(q * (1.f / 256.f) + LN_EPS_F);

    float4 g0 = *(const float4*)(ln_gamma + lane * 4);
    float4 g1 = *(const float4*)(ln_gamma + 128 + lane * 4);
    float4 b0 = *(const float4*)(ln_beta + lane * 4);
    float4 b1 = *(const float4*)(ln_beta + 128 + lane * 4);

    float4 o0, o1;
    o0.x = (a0.x - mu) * rstd * g0.x + b0.x;
    o0.y = (a0.y - mu) * rstd * g0.y + b0.y;
    o0.z = (a0.z - mu) * rstd * g0.z + b0.z;
    o0.w = (a0.w - mu) * rstd * g0.w + b0.w;
    o1.x = (a1.x - mu) * rstd * g1.x + b1.x;
    o1.y = (a1.y - mu) * rstd * g1.y + b1.y;
    o1.z = (a1.z - mu) * rstd * g1.z + b1.z;
    o1.w = (a1.w - mu) * rstd * g1.w + b1.w;

    *(float4*)(rp + lane * 4) = o0;
    *(float4*)(rp + 128 + lane * 4) = o1;
}

// ---------------------------------------------------------------------------
extern "C" void kernel_launch(void* const* d_in, const int* in_sizes, int n_in,
                              void* d_out, int out_size)
{
    const float* x   = (const float*)d_in[0];
    const float* Wq  = (const float*)d_in[1];
    const float* Wk  = (const float*)d_in[2];
    const float* Wv  = (const float*)d_in[3];
    const float* Wqs = (const float*)d_in[4];
    const float* Wks = (const float*)d_in[5];
    const float* Wvs = (const float*)d_in[6];
    const float* lq1 = (const float*)d_in[7];
    const float* lq2 = (const float*)d_in[8];
    const float* lk1 = (const float*)d_in[9];
    const float* lk2 = (const float*)d_in[10];
    const float* gam = (const float*)d_in[11];
    const float* bet = (const float*)d_in[12];

    qkv_gemm<<<dim3(6, 128), 256>>>(x, Wq, Wk, Wv);
    state_fixup<<<64, 256>>>(x, Wqs, Wks, Wvs);
    lambda_kernel<<<1, 32>>>(lq1, lq2, lk1, lk2);

    score_kernel<<<dim3(528, BB), 256>>>();
    reduce_l<<<NROW / 8, 256>>>();
    pv_kernel<<<dim3(64, BB), 256>>>((float*)d_out);
    ln_kernel<<<NROW / 8, 256>>>((float*)d_out, gam, bet);
}

// round 15
// speedup vs baseline: 1.6321x; 1.0148x over previous
#include <cuda_runtime.h>
#include <math.h>
#include <stdint.h>

#define BB 4
#define TT 4096
#define DD 1024
#define NO 256      // 2*dv
#define NROW (BB*TT)
#define LN_EPS_F 1e-5f
#define LAMBDA_INIT 0.3555090675909693f
#define ATT_SCALE 0.0883883476483184405f   // 1/sqrt(128)

typedef unsigned long long u64;

// packed f32x2 helpers (sm_100+ PTX; SASS FFMA2/FADD2)
#define FFMA2(d, a, b) asm("fma.rn.f32x2 %0, %1, %2, %0;" : "+l"(d) : "l"(a), "l"(b))
#define PACK2(d, x)    asm("mov.b64 %0, {%1, %1};" : "=l"(d) : "r"(__float_as_uint(x)))
#define UNPACK2(lo, hi, v) do { unsigned _ul, _uh; \
    asm("mov.b64 {%0, %1}, %2;" : "=r"(_ul), "=r"(_uh) : "l"(v)); \
    (lo) = __uint_as_float(_ul); (hi) = __uint_as_float(_uh); } while (0)

// scratch (device globals: allocation-free rule)
__device__ float g_Q[NROW * NO];
__device__ float g_K[NROW * NO];
__device__ float g_V[NROW * NO];
__device__ float g_P1[67108864];     // [NROW][TT] exp-scores head 1
__device__ float g_P2[67108864];     // [NROW][TT] exp-scores head 2
__device__ float g_Lp[NROW * 64];    // per-(row, keytile, head) partial sums
__device__ float g_Winv[NROW * 2];   // (1/l1, lambda/l2) per row
__device__ float g_lambda;

// ---------------------------------------------------------------------------
// Kernel 1: uniform QKV GEMM, now smem DOUBLE-BUFFERED (1 barrier/chunk).
// C[16384 x 768] = X[16384 x 1024] @ {Wq|Wk|Wv}.  BM=BN=128, BK=16.
// ---------------------------------------------------------------------------
__global__ __launch_bounds__(256) void qkv_gemm(
    const float* __restrict__ x,
    const float* __restrict__ Wq,
    const float* __restrict__ Wk,
    const float* __restrict__ Wv)
{
    __shared__ float Xs[2][16][132];
    __shared__ float Wsm[2][16][128];

    const int nt  = blockIdx.x;
    const int mt  = blockIdx.y;
    const int mat = nt >> 1;
    const int n0  = (nt & 1) * 128;
    const float* W = (mat == 0) ? Wq : ((mat == 1) ? Wk : Wv);
    float* Out     = (mat == 0) ? g_Q : ((mat == 1) ? g_K : g_V);

    const int m0  = mt * 128;
    const int tid = threadIdx.x;
    const int tx  = tid & 15;
    const int ty  = tid >> 4;

    const int xrow = tid >> 2;
    const int xkc  = tid & 3;
    const int wkr  = tid >> 5;
    const int wnc  = tid & 31;

    const float* xp0 = x + (size_t)(m0 + xrow) * DD + xkc * 4;
    const float* xp1 = x + (size_t)(m0 + xrow + 64) * DD + xkc * 4;
    const float* wp0 = W + (size_t)wkr * NO + n0 + wnc * 4;
    const float* wp1 = W + (size_t)(wkr + 8) * NO + n0 + wnc * 4;

    u64 c[4][8];
#pragma unroll
    for (int i = 0; i < 4; i++)
#pragma unroll
        for (int j = 0; j < 8; j++) c[i][j] = 0ull;

    float4 xr0 = *(const float4*)xp0;
    float4 xr1 = *(const float4*)xp1;
    float4 wr0 = *(const float4*)wp0;
    float4 wr1 = *(const float4*)wp1;

    for (int it = 0; it < 64; it++) {
        const int bf = it & 1;
        Xs[bf][xkc * 4 + 0][xrow]      = xr0.x;
        Xs[bf][xkc * 4 + 1][xrow]      = xr0.y;
        Xs[bf][xkc * 4 + 2][xrow]      = xr0.z;
        Xs[bf][xkc * 4 + 3][xrow]      = xr0.w;
        Xs[bf][xkc * 4 + 0][xrow + 64] = xr1.x;
        Xs[bf][xkc * 4 + 1][xrow + 64] = xr1.y;
        Xs[bf][xkc * 4 + 2][xrow + 64] = xr1.z;
        Xs[bf][xkc * 4 + 3][xrow + 64] = xr1.w;
        *(float4*)(&Wsm[bf][wkr][wnc * 4])     = wr0;
        *(float4*)(&Wsm[bf][wkr + 8][wnc * 4]) = wr1;
        __syncthreads();

        if (it < 63) {
            const int k0 = (it + 1) * 16;
            xr0 = *(const float4*)(xp0 + k0);
            xr1 = *(const float4*)(xp1 + k0);
            wr0 = *(const float4*)(wp0 + (size_t)k0 * NO);
            wr1 = *(const float4*)(wp1 + (size_t)k0 * NO);
        }

#pragma unroll
        for (int kk = 0; kk < 16; kk++) {
            ulonglong2 A0 = *(const ulonglong2*)(&Xs[bf][kk][ty * 4]);
            ulonglong2 A1 = *(const ulonglong2*)(&Xs[bf][kk][64 + ty * 4]);
            float4 b0 = *(const float4*)(&Wsm[bf][kk][tx * 4]);
            float4 b1 = *(const float4*)(&Wsm[bf][kk][64 + tx * 4]);
            u64 B[8];
            PACK2(B[0], b0.x); PACK2(B[1], b0.y); PACK2(B[2], b0.z); PACK2(B[3], b0.w);
            PACK2(B[4], b1.x); PACK2(B[5], b1.y); PACK2(B[6], b1.z); PACK2(B[7], b1.w);
#pragma unroll
            for (int j = 0; j < 8; j++) {
                FFMA2(c[0][j], A0.x, B[j]);
                FFMA2(c[1][j], A0.y, B[j]);
                FFMA2(c[2][j], A1.x, B[j]);
                FFMA2(c[3][j], A1.y, B[j]);
            }
        }
    }

#pragma unroll
    for (int rp = 0; rp < 4; rp++) {
        const int r = (rp < 2) ? (ty * 4 + rp * 2) : (64 + ty * 4 + (rp - 2) * 2);
        float lo[8], hi[8];
#pragma unroll
        for (int j = 0; j < 8; j++) UNPACK2(lo[j], hi[j], c[rp][j]);
        float* o0 = Out + (size_t)(m0 + r) * NO + n0;
        float* o1 = o0 + NO;
        *(float4*)(o0 + tx * 4)      = make_float4(lo[0], lo[1], lo[2], lo[3]);
        *(float4*)(o0 + 64 + tx * 4) = make_float4(lo[4], lo[5], lo[6], lo[7]);
        *(float4*)(o1 + tx * 4)      = make_float4(hi[0], hi[1], hi[2], hi[3]);
        *(float4*)(o1 + 64 + tx * 4) = make_float4(hi[4], hi[5], hi[6], hi[7]);
    }
}

// ---------------------------------------------------------------------------
// Kernel 2: recompute the 64 state rows with the *_state weights.
// ---------------------------------------------------------------------------
__global__ __launch_bounds__(256) void state_fixup(
    const float* __restrict__ x,
    const float* __restrict__ Wqs,
    const float* __restrict__ Wks,
    const float* __restrict__ Wvs)
{
    __shared__ float xs[DD];
    const int id = blockIdx.x;
    const int b  = id >> 4;
    const int i  = id & 15;
    const int t  = (i < 8) ? i : (TT - 16 + i);
    const size_t row = (size_t)b * TT + t;
    const int tid = threadIdx.x;

    for (int d = tid; d < DD; d += 256) xs[d] = x[row * DD + d];
    __syncthreads();

    float aq = 0.f, ak = 0.f, av = 0.f;
    const int n = tid;
#pragma unroll 4
    for (int d = 0; d < DD; d++) {
        float xv = xs[d];
        aq += xv * Wqs[(size_t)d * NO + n];
        ak += xv * Wks[(size_t)d * NO + n];
        av += xv * Wvs[(size_t)d * NO + n];
    }
    g_Q[row * NO + n] = aq;
    g_K[row * NO + n] = ak;
    g_V[row * NO + n] = av;
}

// ---------------------------------------------------------------------------
// Kernel 3: lambda scalar
// ---------------------------------------------------------------------------
__global__ void lambda_kernel(const float* __restrict__ lq1,
                              const float* __restrict__ lq2,
                              const float* __restrict__ lk1,
                              const float* __restrict__ lk2)
{
    int lane = threadIdx.x;
    float s1 = 0.f, s2 = 0.f;
    for (int i = lane; i < 128; i += 32) {
        s1 += lq1[i] * lk1[i];
        s2 += lq2[i] * lk2[i];
    }
#pragma unroll
    for (int o = 16; o > 0; o >>= 1) {
        s1 += __shfl_xor_sync(0xffffffffu, s1, o);
        s2 += __shfl_xor_sync(0xffffffffu, s2, o);
    }
    if (lane == 0) g_lambda = expf(s1) - expf(s2) + LAMBDA_INIT;
}

// ---------------------------------------------------------------------------
// Kernel 4 (A): score GEMM (round-14 version, unchanged).
// ---------------------------------------------------------------------------
__global__ __launch_bounds__(256, 2) void score_kernel()
{
    __shared__ float Qs[2][16][132];
    __shared__ float Ks[2][16][132];

    const int b = blockIdx.y;
    const int t = blockIdx.x;
    int r = (int)((sqrtf(8.f * t + 1.f) - 1.f) * 0.5f);
    while ((r + 1) * (r + 2) / 2 <= t) r++;
    while (r * (r + 1) / 2 > t) r--;
    const int kt  = t - r * (r + 1) / 2;
    const int r0g = r * 128;
    const int k0g = kt * 128;
    const size_t rowb = (size_t)b * TT;

    const int tid = threadIdx.x;
    const int tx  = tid & 15;
    const int ty  = tid >> 4;
    const int sdq = tid & 3;
    const int sr0 = tid >> 2;

    const float* qb0 = g_Q + (rowb + r0g + sr0) * NO + sdq * 4;
    const float* qb1 = qb0 + (size_t)64 * NO;
    const float* kb0 = g_K + (rowb + k0g + sr0) * NO + sdq * 4;
    const float* kb1 = kb0 + (size_t)64 * NO;

    float4 pq[2], pk[2];
#define SLOADG(g) do { \
        int db_ = (((g) >> 3) * 128) + (((g) & 7) * 16); \
        pq[0] = *(const float4*)(qb0 + db_); \
        pq[1] = *(const float4*)(qb1 + db_); \
        pk[0] = *(const float4*)(kb0 + db_); \
        pk[1] = *(const float4*)(kb1 + db_); \
    } while (0)

    u64 c[4][8];
#pragma unroll
    for (int i = 0; i < 4; i++)
#pragma unroll
        for (int j = 0; j < 8; j++) c[i][j] = 0ull;

    SLOADG(0);

    for (int g = 0; g < 16; g++) {
        const int bf = g & 1;
#pragma unroll
        for (int i = 0; i < 2; i++) {
            int row = sr0 + i * 64;
            Qs[bf][sdq * 4 + 0][row] = pq[i].x * ATT_SCALE;
            Qs[bf][sdq * 4 + 1][row] = pq[i].y * ATT_SCALE;
            Qs[bf][sdq * 4 + 2][row] = pq[i].z * ATT_SCALE;
            Qs[bf][sdq * 4 + 3][row] = pq[i].w * ATT_SCALE;
            Ks[bf][sdq * 4 + 0][row] = pk[i].x;
            Ks[bf][sdq * 4 + 1][row] = pk[i].y;
            Ks[bf][sdq * 4 + 2][row] = pk[i].z;
            Ks[bf][sdq * 4 + 3][row] = pk[i].w;
        }
        __syncthreads();
        if (g < 15) SLOADG(g + 1);

#pragma unroll
        for (int kk = 0; kk < 16; kk++) {
            ulonglong2 A0 = *(const ulonglong2*)(&Qs[bf][kk][ty * 4]);
            ulonglong2 A1 = *(const ulonglong2*)(&Qs[bf][kk][64 + ty * 4]);
            float4 b0 = *(const float4*)(&Ks[bf][kk][tx * 4]);
            float4 b1 = *(const float4*)(&Ks[bf][kk][64 + tx * 4]);
            u64 B[8];
            PACK2(B[0], b0.x); PACK2(B[1], b0.y); PACK2(B[2], b0.z); PACK2(B[3], b0.w);
            PACK2(B[4], b1.x); PACK2(B[5], b1.y); PACK2(B[6], b1.z); PACK2(B[7], b1.w);
#pragma unroll
            for (int j = 0; j < 8; j++) {
                FFMA2(c[0][j], A0.x, B[j]);
                FFMA2(c[1][j], A0.y, B[j]);
                FFMA2(c[2][j], A1.x, B[j]);
                FFMA2(c[3][j], A1.y, B[j]);
            }
        }

        if ((g & 7) == 7) {
            const int ph = g >> 3;
            float* Pout = ph ? g_P2 : g_P1;
#pragma unroll
            for (int rp = 0; rp < 4; rp++) {
                const int rl = (rp < 2) ? (ty * 4 + rp * 2)
                                        : (64 + ty * 4 + (rp - 2) * 2);
                float lo[8], hi[8];
#pragma unroll
                for (int j = 0; j < 8; j++) UNPACK2(lo[j], hi[j], c[rp][j]);

#pragma unroll
                for (int e = 0; e < 2; e++) {
                    const int rg = r0g + rl + e;
                    const float* v = e ? hi : lo;
                    float p[8];
#pragma unroll
                    for (int j = 0; j < 8; j++) {
                        int key = k0g + ((j < 4) ? (tx * 4 + j)
                                                 : (64 + tx * 4 + j - 4));
                        p[j] = (key <= rg) ? __expf(v[j]) : 0.f;
                    }
                    float* Pp = Pout + (rowb + rg) * (size_t)TT + k0g;
                    *(float4*)(Pp + tx * 4)      = make_float4(p[0], p[1], p[2], p[3]);
                    *(float4*)(Pp + 64 + tx * 4) = make_float4(p[4], p[5], p[6], p[7]);
                    float rs = p[0] + p[1] + p[2] + p[3] + p[4] + p[5] + p[6] + p[7];
                    rs += __shfl_xor_sync(0xffffffffu, rs, 1);
                    rs += __shfl_xor_sync(0xffffffffu, rs, 2);
                    rs += __shfl_xor_sync(0xffffffffu, rs, 4);
                    rs += __shfl_xor_sync(0xffffffffu, rs, 8);
                    if (tx == 0)
                        g_Lp[(rowb + rg) * 64 + kt * 2 + ph] = rs;
                }
            }
#pragma unroll
            for (int i = 0; i < 4; i++)
#pragma unroll
                for (int j = 0; j < 8; j++) c[i][j] = 0ull;
        }
    }
#undef SLOADG
}

// ---------------------------------------------------------------------------
// Kernel 5 (R): reduce per-tile partials -> (1/l1, lambda/l2) per row.
// ---------------------------------------------------------------------------
__global__ __launch_bounds__(256) void reduce_l()
{
    const int row  = blockIdx.x * 8 + (threadIdx.x >> 5);
    const int lane = threadIdx.x & 31;
    const int rib  = row & (TT - 1);
    const int nk   = (rib >> 7) + 1;

    float v1 = 0.f, v2 = 0.f;
    if (lane < nk) {
        v1 = g_Lp[(size_t)row * 64 + 2 * lane];
        v2 = g_Lp[(size_t)row * 64 + 2 * lane + 1];
    }
#pragma unroll
    for (int o = 16; o > 0; o >>= 1) {
        v1 += __shfl_xor_sync(0xffffffffu, v1, o);
        v2 += __shfl_xor_sync(0xffffffffu, v2, o);
    }
    if (lane == 0) {
        g_Winv[row * 2]     = 1.f / v1;
        g_Winv[row * 2 + 1] = g_lambda / v2;
    }
}

// ---------------------------------------------------------------------------
// Kernel 6 (B): PV GEMM + FUSED LayerNorm.  32 rows x 256 dims per tile,
// reg prefetch + smem double-buffer.  W = i1*P1 - li2*P2 at staging.
// LN row stats via smem reduction reusing the dead Ws buffers.
// Pair-balanced row-tiles (p, 127-p): 129 chunks/CTA.  grid (64, BB).
// ---------------------------------------------------------------------------
__global__ __launch_bounds__(256, 2) void pv_kernel(
    float* __restrict__ out,
    const float* __restrict__ ln_gamma,
    const float* __restrict__ ln_beta)
{
    __shared__ float Ws[2][32][34];    // [buf][key][row]; reused for LN reduction
    __shared__ float Vs[2][32][260];   // [buf][key][dim]
    __shared__ float Wi2[64];          // staging scales; reused for mu/rstd

    const int b    = blockIdx.y;
    const int p    = blockIdx.x;       // 0..63
    const size_t rowb = (size_t)b * TT;

    const int tid = threadIdx.x;
    const int tx  = tid & 7;           // row group (4 rows)
    const int ty  = tid >> 3;          // dim group (8 dims)
    const int wr  = tid >> 3;          // W staging row (0..31)
    const int wkq = tid & 7;           // W staging k-quad

    // LN params for this thread's 8 dims (dims ty*8 .. ty*8+7)
    float g8[8], b8[8];
#pragma unroll
    for (int k = 0; k < 8; k++) {
        g8[k] = ln_gamma[ty * 8 + k];
        b8[k] = ln_beta[ty * 8 + k];
    }

    float* redS = &Ws[0][0][0];        // [32][33] partial sums
    float* redQ = redS + 32 * 33;      // [32][33] partial sumsq (fits in Ws: 2176 floats)
    float* muA  = Wi2;                 // [32]
    float* rsA  = Wi2 + 32;            // [32]

    float4 pp1, pp2, pv4[8];

#pragma unroll 1
    for (int pass = 0; pass < 2; pass++) {
        const int r   = pass ? (127 - p) : p;
        const int t0  = r * 32;
        const int nch = r + 1;

#define PVLOAD(ch) do { \
            int kb_ = (ch) * 32; \
            size_t po_ = (rowb + t0 + wr) * (size_t)TT + kb_ + wkq * 4; \
            pp1 = *(const float4*)(g_P1 + po_); \
            pp2 = *(const float4*)(g_P2 + po_); \
            _Pragma("unroll") \
            for (int i_ = 0; i_ < 8; i_++) { \
                int idx_ = tid + i_ * 256; \
                int key_ = idx_ >> 6; \
                int dq_  = idx_ & 63; \
                pv4[i_] = *(const float4*)(g_V + (rowb + kb_ + key_) * NO + dq_ * 4); \
            } \
        } while (0)

        __syncthreads();               // previous pass fully done with smem
        if (tid < 32) {
            float2 wv = *(const float2*)(g_Winv + (rowb + t0 + tid) * 2);
            Wi2[tid * 2]     = wv.x;
            Wi2[tid * 2 + 1] = wv.y;
        }
        PVLOAD(0);

        u64 c[2][8];
#pragma unroll
        for (int i = 0; i < 2; i++)
#pragma unroll
            for (int j = 0; j < 8; j++) c[i][j] = 0ull;

        __syncthreads();               // Wi2 visible

        for (int ch = 0; ch < nch; ch++) {
            const int bf = ch & 1;
            {
                float i1  = Wi2[wr * 2];
                float li2 = Wi2[wr * 2 + 1];
                Ws[bf][wkq * 4 + 0][wr] = pp1.x * i1 - pp2.x * li2;
                Ws[bf][wkq * 4 + 1][wr] = pp1.y * i1 - pp2.y * li2;
                Ws[bf][wkq * 4 + 2][wr] = pp1.z * i1 - pp2.z * li2;
                Ws[bf][wkq * 4 + 3][wr] = pp1.w * i1 - pp2.w * li2;
            }
#pragma unroll
            for (int i = 0; i < 8; i++) {
                int idx = tid + i * 256;
                int key = idx >> 6;
                int dq  = idx & 63;
                *(float4*)(&Vs[bf][key][dq * 4]) = pv4[i];
            }
            __syncthreads();

            if (ch + 1 < nch) PVLOAD(ch + 1);

#pragma unroll 4
            for (int kk = 0; kk < 32; kk++) {
                u64 aLo = *(const u64*)(&Ws[bf][kk][tx * 4]);
                u64 aHi = *(const u64*)(&Ws[bf][kk][tx * 4 + 2]);
                float4 b0 = *(const float4*)(&Vs[bf][kk][ty * 8]);
                float4 b1 = *(const float4*)(&Vs[bf][kk][ty * 8 + 4]);
                u64 B[8];
                PACK2(B[0], b0.x); PACK2(B[1], b0.y); PACK2(B[2], b0.z); PACK2(B[3], b0.w);
                PACK2(B[4], b1.x); PACK2(B[5], b1.y); PACK2(B[6], b1.z); PACK2(B[7], b1.w);
#pragma unroll
                for (int j = 0; j < 8; j++) {
                    FFMA2(c[0][j], aLo, B[j]);
                    FFMA2(c[1][j], aHi, B[j]);
                }
            }
        }
#undef PVLOAD

        // -------- fused LayerNorm epilogue --------
        float lo[2][8], hi[2][8];
#pragma unroll
        for (int rp = 0; rp < 2; rp++)
#pragma unroll
            for (int j = 0; j < 8; j++) UNPACK2(lo[rp][j], hi[rp][j], c[rp][j]);

        // local partials over this thread's 8 dims, 4 rows
        float ps[4] = {0.f, 0.f, 0.f, 0.f}, pq[4] = {0.f, 0.f, 0.f, 0.f};
#pragma unroll
        for (int rp = 0; rp < 2; rp++)
#pragma unroll
            for (int j = 0; j < 8; j++) {
                float a = lo[rp][j], h = hi[rp][j];
                ps[2 * rp]     += a;  pq[2 * rp]     += a * a;
                ps[2 * rp + 1] += h;  pq[2 * rp + 1] += h * h;
            }

        __syncthreads();               // all compute reads of Ws done
#pragma unroll
        for (int rr = 0; rr < 4; rr++) {
            int row = tx * 4 + ((rr < 2) ? (2 * (rr & 1)) : (2 * (rr & 1) + 1));
            // rows owned: tx*4 + 2*rp + e ; map rr -> (rp, e): rr = 2*rp + e
            row = tx * 4 + rr;         // ps index: rr == 2*rp+e matches row offset
            redS[row * 33 + ty] = ps[rr];
            redQ[row * 33 + ty] = pq[rr];
        }
        __syncthreads();
        if (tid < 32) {
            float s = 0.f, q = 0.f;
#pragma unroll 8
            for (int j = 0; j < 32; j++) {
                s += redS[tid * 33 + j];
                q += redQ[tid * 33 + j];
            }
            float mu = s * (1.f / 256.f);
            muA[tid] = mu;
            rsA[tid] = rsqrtf(q * (1.f / 256.f) - mu * mu + LN_EPS_F);
        }
        __syncthreads();

#pragma unroll
        for (int rp = 0; rp < 2; rp++) {
            const int rl0 = tx * 4 + 2 * rp;
            float mu0 = muA[rl0],     rs0 = rsA[rl0];
            float mu1 = muA[rl0 + 1], rs1 = rsA[rl0 + 1];
            float* o0 = out + (rowb + t0 + rl0) * NO + ty * 8;
            float* o1 = o0 + NO;
            float4 w0, w1, w2, w3;
            w0.x = (lo[rp][0] - mu0) * rs0 * g8[0] + b8[0];
            w0.y = (lo[rp][1] - mu0) * rs0 * g8[1] + b8[1];
            w0.z = (lo[rp][2] - mu0) * rs0 * g8[2] + b8[2];
            w0.w = (lo[rp][3] - mu0) * rs0 * g8[3] + b8[3];
            w1.x = (lo[rp][4] - mu0) * rs0 * g8[4] + b8[4];
            w1.y = (lo[rp][5] - mu0) * rs0 * g8[5] + b8[5];
            w1.z = (lo[rp][6] - mu0) * rs0 * g8[6] + b8[6];
            w1.w = (lo[rp][7] - mu0) * rs0 * g8[7] + b8[7];
            w2.x = (hi[rp][0] - mu1) * rs1 * g8[0] + b8[0];
            w2.y = (hi[rp][1] - mu1) * rs1 * g8[1] + b8[1];
            w2.z = (hi[rp][2] - mu1) * rs1 * g8[2] + b8[2];
            w2.w = (hi[rp][3] - mu1) * rs1 * g8[3] + b8[3];
            w3.x = (hi[rp][4] - mu1) * rs1 * g8[4] + b8[4];
            w3.y = (hi[rp][5] - mu1) * rs1 * g8[5] + b8[5];
            w3.z = (hi[rp][6] - mu1) * rs1 * g8[6] + b8[6];
            w3.w = (hi[rp][7] - mu1) * rs1 * g8[7] + b8[7];
            *(float4*)(o0)     = w0;
            *(float4*)(o0 + 4) = w1;
            *(float4*)(o1)     = w2;
            *(float4*)(o1 + 4) = w3;
        }
    }
}

// ---------------------------------------------------------------------------
extern "C" void kernel_launch(void* const* d_in, const int* in_sizes, int n_in,
                              void* d_out, int out_size)
{
    const float* x   = (const float*)d_in[0];
    const float* Wq  = (const float*)d_in[1];
    const float* Wk  = (const float*)d_in[2];
    const float* Wv  = (const float*)d_in[3];
    const float* Wqs = (const float*)d_in[4];
    const float* Wks = (const float*)d_in[5];
    const float* Wvs = (const float*)d_in[6];
    const float* lq1 = (const float*)d_in[7];
    const float* lq2 = (const float*)d_in[8];
    const float* lk1 = (const float*)d_in[9];
    const float* lk2 = (const float*)d_in[10];
    const float* gam = (const float*)d_in[11];
    const float* bet = (const float*)d_in[12];

    qkv_gemm<<<dim3(6, 128), 256>>>(x, Wq, Wk, Wv);
    state_fixup<<<64, 256>>>(x, Wqs, Wks, Wvs);
    lambda_kernel<<<1, 32>>>(lq1, lq2, lk1, lk2);

    score_kernel<<<dim3(528, BB), 256>>>();
    reduce_l<<<NROW / 8, 256>>>();
    pv_kernel<<<dim3(64, BB), 256>>>((float*)d_out, gam, bet);
}